// round 1
// baseline (speedup 1.0000x reference)
#include <cuda_runtime.h>
#include <math.h>

#define S_LEN 2048
#define HIDDEN 2048
#define NHEAD 16
#define HDIM 128
#define RDIM 64
#define KVC 512
#define QC 1024
#define DTOT 192           // HDIM + RDIM
#define KROW (NHEAD*DTOT)  // 3072
#define VROW (NHEAD*HDIM)  // 2048

// ---------------- scratch (device globals; no allocation allowed) ----------
__device__ float g_kv_c[S_LEN * KVC];
__device__ float g_q_c[S_LEN * QC];
__device__ float g_keys[S_LEN * KROW];
__device__ float g_queries[S_LEN * KROW];
__device__ float g_values[S_LEN * VROW];
__device__ float g_rope_raw[S_LEN * NHEAD * RDIM];
__device__ float g_ctx[S_LEN * VROW];

// ---------------- generic NT SGEMM: C = A[M,K] * B[N,K]^T + bias[N] --------
// Output address: m*row_stride + (n/G)*GS + (n%G) + CO  (head-scatter epilogue)
__global__ __launch_bounds__(256) void sgemm_nt(
    const float* __restrict__ A, const float* __restrict__ B,
    const float* __restrict__ bias, float* __restrict__ C,
    int M, int N, int K, int row_stride, int G, int GS, int CO)
{
    __shared__ float As[8][128];
    __shared__ float Bs[8][128];
    const int tid = threadIdx.x;
    const int tx = tid & 15, ty = tid >> 4;
    const int bm = blockIdx.y * 128, bn = blockIdx.x * 128;
    const int sr = tid >> 1;            // 0..127
    const int sc = (tid & 1) << 2;      // 0 or 4
    const float* Ap = A + (size_t)(bm + sr) * K + sc;
    const float* Bp = B + (size_t)(bn + sr) * K + sc;

    float acc[8][8];
#pragma unroll
    for (int i = 0; i < 8; i++)
#pragma unroll
        for (int j = 0; j < 8; j++) acc[i][j] = 0.f;

    for (int k0 = 0; k0 < K; k0 += 8) {
        float4 av = *(const float4*)(Ap + k0);
        float4 bv = *(const float4*)(Bp + k0);
        As[sc + 0][sr] = av.x; As[sc + 1][sr] = av.y;
        As[sc + 2][sr] = av.z; As[sc + 3][sr] = av.w;
        Bs[sc + 0][sr] = bv.x; Bs[sc + 1][sr] = bv.y;
        Bs[sc + 2][sr] = bv.z; Bs[sc + 3][sr] = bv.w;
        __syncthreads();
#pragma unroll
        for (int k = 0; k < 8; k++) {
            float ar[8], br[8];
            *(float4*)&ar[0] = *(const float4*)&As[k][ty * 8];
            *(float4*)&ar[4] = *(const float4*)&As[k][ty * 8 + 4];
            *(float4*)&br[0] = *(const float4*)&Bs[k][tx * 8];
            *(float4*)&br[4] = *(const float4*)&Bs[k][tx * 8 + 4];
#pragma unroll
            for (int i = 0; i < 8; i++)
#pragma unroll
                for (int j = 0; j < 8; j++)
                    acc[i][j] += ar[i] * br[j];
        }
        __syncthreads();
    }

#pragma unroll
    for (int i = 0; i < 8; i++) {
        int m = bm + ty * 8 + i;
#pragma unroll
        for (int j = 0; j < 8; j += 4) {
            int n = bn + tx * 8 + j;
            float4 v;
            v.x = acc[i][j + 0] + bias[n + 0];
            v.y = acc[i][j + 1] + bias[n + 1];
            v.z = acc[i][j + 2] + bias[n + 2];
            v.w = acc[i][j + 3] + bias[n + 3];
            size_t off = (size_t)m * row_stride + (size_t)(n / G) * GS + (n % G) + CO;
            *(float4*)(C + off) = v;
        }
    }
}

// ---------------- RoPE (positions = head index, per reference) -------------
// raw: [S, NHEAD*RDIM]; dst: write at s*KROW + h*DTOT + HDIM + {2i, 2i+1}
__global__ void rope_kernel(const float* __restrict__ raw, float* __restrict__ dst)
{
    int idx = blockIdx.x * blockDim.x + threadIdx.x;
    if (idx >= S_LEN * NHEAD * (RDIM / 2)) return;
    int i = idx & 31;            // freq index 0..31
    int h = (idx >> 5) & 15;     // head
    int s = idx >> 9;            // seq
    size_t rb = (size_t)s * (NHEAD * RDIM) + h * RDIM + 2 * i;
    float x1 = raw[rb], x2 = raw[rb + 1];
    float inv_freq = powf(10000.f, -((float)(2 * i)) / (float)RDIM);
    float ang = (float)h * inv_freq;
    float sv, cv;
    sincosf(ang, &sv, &cv);
    size_t ob = (size_t)s * KROW + h * DTOT + HDIM + 2 * i;
    dst[ob]     = x1 * cv - x2 * sv;
    dst[ob + 1] = x1 * sv + x2 * cv;
}

// ---------------- fused flash attention (fp32) -----------------------------
// grid (S/64, NHEAD), 256 threads. Q tile held in smem across all K tiles.
#define QPAD 193
#define SPAD 65
#define ATTN_SMEM_FLOATS (64*QPAD*2 + 64*128 + 64*SPAD + 3*64)
#define ATTN_SMEM_BYTES  (ATTN_SMEM_FLOATS * 4)

__global__ __launch_bounds__(256) void attn_kernel(
    const float* __restrict__ Qg, const float* __restrict__ Kg,
    const float* __restrict__ Vg, float* __restrict__ Og)
{
    extern __shared__ float sm[];
    float* Qs    = sm;                 // [64][QPAD]
    float* Ks    = Qs + 64 * QPAD;     // [64][QPAD]
    float* Vs    = Ks + 64 * QPAD;     // [64][128]
    float* Ss    = Vs + 64 * 128;      // [64][SPAD]
    float* row_m = Ss + 64 * SPAD;
    float* row_l = row_m + 64;
    float* row_c = row_l + 64;

    const int tid = threadIdx.x;
    const int tx = tid & 15, ty = tid >> 4;
    const int h = blockIdx.y;
    const int q0 = blockIdx.x * 64;
    const float scale = 1.f / sqrtf((float)DTOT);

    // Load Q tile [64 x 192]
    for (int idx = tid; idx < 64 * 48; idx += 256) {
        int r = idx / 48, c4 = (idx % 48) * 4;
        float4 v = *(const float4*)(Qg + (size_t)(q0 + r) * KROW + h * DTOT + c4);
        float* p = &Qs[r * QPAD + c4];
        p[0] = v.x; p[1] = v.y; p[2] = v.z; p[3] = v.w;
    }
    if (tid < 64) { row_m[tid] = -INFINITY; row_l[tid] = 0.f; }

    float acc[4][8];
#pragma unroll
    for (int i = 0; i < 4; i++)
#pragma unroll
        for (int j = 0; j < 8; j++) acc[i][j] = 0.f;

    for (int t = 0; t < S_LEN / 64; t++) {
        const int k0 = t * 64;
        __syncthreads();   // previous iteration done with Ks/Vs/Ss
        // Load K tile [64 x 192]
        for (int idx = tid; idx < 64 * 48; idx += 256) {
            int r = idx / 48, c4 = (idx % 48) * 4;
            float4 v = *(const float4*)(Kg + (size_t)(k0 + r) * KROW + h * DTOT + c4);
            float* p = &Ks[r * QPAD + c4];
            p[0] = v.x; p[1] = v.y; p[2] = v.z; p[3] = v.w;
        }
        // Load V tile [64 x 128]
        for (int idx = tid; idx < 64 * 32; idx += 256) {
            int r = idx / 32, c4 = (idx % 32) * 4;
            float4 v = *(const float4*)(Vg + (size_t)(k0 + r) * VROW + h * HDIM + c4);
            *(float4*)&Vs[r * 128 + c4] = v;
        }
        __syncthreads();

        // S = Q * K^T  (each thread 4x4)
        float s4[4][4];
#pragma unroll
        for (int i = 0; i < 4; i++)
#pragma unroll
            for (int j = 0; j < 4; j++) s4[i][j] = 0.f;
#pragma unroll 4
        for (int d = 0; d < DTOT; d++) {
            float ar[4], br[4];
#pragma unroll
            for (int i = 0; i < 4; i++) ar[i] = Qs[(ty * 4 + i) * QPAD + d];
#pragma unroll
            for (int j = 0; j < 4; j++) br[j] = Ks[(tx * 4 + j) * QPAD + d];
#pragma unroll
            for (int i = 0; i < 4; i++)
#pragma unroll
                for (int j = 0; j < 4; j++)
                    s4[i][j] += ar[i] * br[j];
        }
#pragma unroll
        for (int i = 0; i < 4; i++)
#pragma unroll
            for (int j = 0; j < 4; j++)
                Ss[(ty * 4 + i) * SPAD + tx * 4 + j] = s4[i][j] * scale;
        __syncthreads();

        // Online softmax: 4 threads per row
        {
            int r = tid >> 2, q = tid & 3;
            float mloc = -INFINITY;
            const float* srow = &Ss[r * SPAD + q * 16];
#pragma unroll
            for (int c = 0; c < 16; c++) mloc = fmaxf(mloc, srow[c]);
            mloc = fmaxf(mloc, __shfl_xor_sync(0xffffffffu, mloc, 1));
            mloc = fmaxf(mloc, __shfl_xor_sync(0xffffffffu, mloc, 2));
            float m_old = row_m[r];
            float m_new = fmaxf(m_old, mloc);
            float lsum = 0.f;
            float* swrow = &Ss[r * SPAD + q * 16];
#pragma unroll
            for (int c = 0; c < 16; c++) {
                float p = __expf(swrow[c] - m_new);
                swrow[c] = p;
                lsum += p;
            }
            lsum += __shfl_xor_sync(0xffffffffu, lsum, 1);
            lsum += __shfl_xor_sync(0xffffffffu, lsum, 2);
            if (q == 0) {
                row_c[r] = __expf(m_old - m_new);
                row_m[r] = m_new;
                row_l[r] = row_l[r] * row_c[r] + lsum;
            }
        }
        __syncthreads();

        // Rescale accumulators, then O += P * V
        float cr[4];
#pragma unroll
        for (int i = 0; i < 4; i++) cr[i] = row_c[ty * 4 + i];
#pragma unroll
        for (int i = 0; i < 4; i++)
#pragma unroll
            for (int j = 0; j < 8; j++) acc[i][j] *= cr[i];

#pragma unroll 4
        for (int k = 0; k < 64; k++) {
            float p[4], v[8];
#pragma unroll
            for (int i = 0; i < 4; i++) p[i] = Ss[(ty * 4 + i) * SPAD + k];
            *(float4*)&v[0] = *(const float4*)&Vs[k * 128 + tx * 8];
            *(float4*)&v[4] = *(const float4*)&Vs[k * 128 + tx * 8 + 4];
#pragma unroll
            for (int i = 0; i < 4; i++)
#pragma unroll
                for (int j = 0; j < 8; j++)
                    acc[i][j] += p[i] * v[j];
        }
    }
    __syncthreads();

    float inv_l[4];
#pragma unroll
    for (int i = 0; i < 4; i++) inv_l[i] = 1.f / row_l[ty * 4 + i];
#pragma unroll
    for (int i = 0; i < 4; i++) {
        int r = q0 + ty * 4 + i;
#pragma unroll
        for (int j = 0; j < 8; j += 4) {
            float4 o;
            o.x = acc[i][j + 0] * inv_l[i];
            o.y = acc[i][j + 1] * inv_l[i];
            o.z = acc[i][j + 2] * inv_l[i];
            o.w = acc[i][j + 3] * inv_l[i];
            *(float4*)(Og + (size_t)r * VROW + h * HDIM + tx * 8 + j) = o;
        }
    }
}

// ---------------- launcher -------------------------------------------------
extern "C" void kernel_launch(void* const* d_in, const int* in_sizes, int n_in,
                              void* d_out, int out_size)
{
    const float* x            = (const float*)d_in[0];
    const float* kv_down_w    = (const float*)d_in[1];
    const float* kv_down_b    = (const float*)d_in[2];
    const float* key_up_w     = (const float*)d_in[3];
    const float* key_up_b     = (const float*)d_in[4];
    const float* value_up_w   = (const float*)d_in[5];
    const float* value_up_b   = (const float*)d_in[6];
    const float* key_rope_w   = (const float*)d_in[7];
    const float* key_rope_b   = (const float*)d_in[8];
    const float* query_down_w = (const float*)d_in[9];
    const float* query_down_b = (const float*)d_in[10];
    const float* query_up_w   = (const float*)d_in[11];
    const float* query_up_b   = (const float*)d_in[12];
    const float* query_rope_w = (const float*)d_in[13];
    const float* query_rope_b = (const float*)d_in[14];
    const float* out_w        = (const float*)d_in[15];
    const float* out_b        = (const float*)d_in[16];
    float* out = (float*)d_out;

    float *kv_c, *q_c, *keys, *queries, *values, *rraw, *ctx;
    cudaGetSymbolAddress((void**)&kv_c,    g_kv_c);
    cudaGetSymbolAddress((void**)&q_c,     g_q_c);
    cudaGetSymbolAddress((void**)&keys,    g_keys);
    cudaGetSymbolAddress((void**)&queries, g_queries);
    cudaGetSymbolAddress((void**)&values,  g_values);
    cudaGetSymbolAddress((void**)&rraw,    g_rope_raw);
    cudaGetSymbolAddress((void**)&ctx,     g_ctx);

    const dim3 blk(256);

    // 1. kv_c = x @ kv_down_w^T            [S, 512]
    sgemm_nt<<<dim3(KVC / 128, S_LEN / 128), blk>>>(
        x, kv_down_w, kv_down_b, kv_c, S_LEN, KVC, HIDDEN, KVC, KVC, 0, 0);
    // 2. q_c = x @ query_down_w^T          [S, 1024]
    sgemm_nt<<<dim3(QC / 128, S_LEN / 128), blk>>>(
        x, query_down_w, query_down_b, q_c, S_LEN, QC, HIDDEN, QC, QC, 0, 0);
    // 3. keys_c -> keys[:, h, 0:128]
    sgemm_nt<<<dim3((NHEAD * HDIM) / 128, S_LEN / 128), blk>>>(
        kv_c, key_up_w, key_up_b, keys, S_LEN, NHEAD * HDIM, KVC, KROW, HDIM, DTOT, 0);
    // 4. values                            [S, 2048]
    sgemm_nt<<<dim3((NHEAD * HDIM) / 128, S_LEN / 128), blk>>>(
        kv_c, value_up_w, value_up_b, values, S_LEN, NHEAD * HDIM, KVC, VROW, VROW, 0, 0);
    // 5. key rope raw, then rope scatter -> keys[:, h, 128:192]
    sgemm_nt<<<dim3((NHEAD * RDIM) / 128, S_LEN / 128), blk>>>(
        kv_c, key_rope_w, key_rope_b, rraw, S_LEN, NHEAD * RDIM, KVC,
        NHEAD * RDIM, NHEAD * RDIM, 0, 0);
    {
        int n = S_LEN * NHEAD * (RDIM / 2);
        rope_kernel<<<(n + 255) / 256, 256>>>(rraw, keys);
    }
    // 6. queries_c -> queries[:, h, 0:128]
    sgemm_nt<<<dim3((NHEAD * HDIM) / 128, S_LEN / 128), blk>>>(
        q_c, query_up_w, query_up_b, queries, S_LEN, NHEAD * HDIM, QC, KROW, HDIM, DTOT, 0);
    // 7. query rope raw, then rope scatter -> queries[:, h, 128:192]
    sgemm_nt<<<dim3((NHEAD * RDIM) / 128, S_LEN / 128), blk>>>(
        q_c, query_rope_w, query_rope_b, rraw, S_LEN, NHEAD * RDIM, QC,
        NHEAD * RDIM, NHEAD * RDIM, 0, 0);
    {
        int n = S_LEN * NHEAD * (RDIM / 2);
        rope_kernel<<<(n + 255) / 256, 256>>>(rraw, queries);
    }
    // 8. attention -> ctx [S, 2048]
    cudaFuncSetAttribute(attn_kernel, cudaFuncAttributeMaxDynamicSharedMemorySize,
                         ATTN_SMEM_BYTES);
    attn_kernel<<<dim3(S_LEN / 64, NHEAD), blk, ATTN_SMEM_BYTES>>>(
        queries, keys, values, ctx);
    // 9. out = ctx @ out_w^T + out_b       [S, 2048]
    sgemm_nt<<<dim3(HIDDEN / 128, S_LEN / 128), blk>>>(
        ctx, out_w, out_b, out, S_LEN, HIDDEN, NHEAD * HDIM, HIDDEN, HIDDEN, 0, 0);
}

// round 4
// speedup vs baseline: 1.4458x; 1.4458x over previous
#include <cuda_runtime.h>
#include <cuda_bf16.h>
#include <math.h>
#include <stdint.h>

#define S_LEN 2048
#define HIDDEN 2048
#define NHEAD 16
#define HDIM 128
#define RDIM 64
#define KVC 512
#define QC 1024
#define DTOT 192           // HDIM + RDIM
#define KROW (NHEAD*DTOT)  // 3072
#define VROW (NHEAD*HDIM)  // 2048

// ---------------- fp32 scratch ---------------------------------------------
__device__ float g_kv_c[S_LEN * KVC];
__device__ float g_q_c[S_LEN * QC];
__device__ float g_keys[S_LEN * KROW];
__device__ float g_queries[S_LEN * KROW];
__device__ float g_values[S_LEN * VROW];
__device__ float g_rope_raw[S_LEN * NHEAD * RDIM];
__device__ float g_ctx[S_LEN * VROW];

// ---------------- bf16x3 operand scratch -----------------------------------
__device__ __align__(1024) __nv_bfloat16 g_x2   [S_LEN * 3 * HIDDEN];
__device__ __align__(1024) __nv_bfloat16 g_kvc2 [S_LEN * 3 * KVC];
__device__ __align__(1024) __nv_bfloat16 g_qc2  [S_LEN * 3 * QC];
__device__ __align__(1024) __nv_bfloat16 g_ctx2 [S_LEN * 3 * VROW];
__device__ __align__(1024) __nv_bfloat16 g_w_kvd[KVC * 3 * HIDDEN];
__device__ __align__(1024) __nv_bfloat16 g_w_qd [QC * 3 * HIDDEN];
__device__ __align__(1024) __nv_bfloat16 g_w_ku [VROW * 3 * KVC];
__device__ __align__(1024) __nv_bfloat16 g_w_vu [VROW * 3 * KVC];
__device__ __align__(1024) __nv_bfloat16 g_w_kr [(NHEAD*RDIM) * 3 * KVC];
__device__ __align__(1024) __nv_bfloat16 g_w_qu [VROW * 3 * QC];
__device__ __align__(1024) __nv_bfloat16 g_w_qr [(NHEAD*RDIM) * 3 * QC];
__device__ __align__(1024) __nv_bfloat16 g_w_out[HIDDEN * 3 * VROW];

// ---------------- mma.sync helpers (sm_80 baseline PTX) --------------------
__device__ __forceinline__ uint32_t smem_u32(const void* p) {
    uint32_t a;
    asm("{ .reg .u64 t; cvta.to.shared.u64 t, %1; cvt.u32.u64 %0, t; }" : "=r"(a) : "l"(p));
    return a;
}
__device__ __forceinline__ void ldsm4(uint32_t* r, uint32_t addr) {
    asm volatile("ldmatrix.sync.aligned.m8n8.x4.shared.b16 {%0,%1,%2,%3}, [%4];"
                 : "=r"(r[0]), "=r"(r[1]), "=r"(r[2]), "=r"(r[3]) : "r"(addr));
}
__device__ __forceinline__ void mma16816(float* d, const uint32_t* a, uint32_t b0, uint32_t b1) {
    asm volatile("mma.sync.aligned.m16n8k16.row.col.f32.bf16.bf16.f32 "
                 "{%0,%1,%2,%3}, {%4,%5,%6,%7}, {%8,%9}, {%0,%1,%2,%3};"
                 : "+f"(d[0]), "+f"(d[1]), "+f"(d[2]), "+f"(d[3])
                 : "r"(a[0]), "r"(a[1]), "r"(a[2]), "r"(a[3]), "r"(b0), "r"(b1));
}
#define CP_ASYNC16(dst, src) \
    asm volatile("cp.async.cg.shared.global [%0], [%1], 16;" :: "r"(dst), "l"(src))
#define CP_COMMIT() asm volatile("cp.async.commit_group;" ::: "memory")
#define CP_WAIT2()  asm volatile("cp.async.wait_group 2;" ::: "memory")

// smem tile: 128 rows x 64 bytes (32 bf16), swizzled 16B unit: c ^= (r>>1)&3
#define NSTAGE 4
#define STAGE_BYTES 8192
#define GEMM_SMEM_BYTES (NSTAGE * STAGE_BYTES * 2)   // 65536

// ---------------- mma.sync NT GEMM: C = A[M,K']*B[N,K']^T + bias -----------
// scatter epilogue: addr = m*row_stride + (n/G)*GS + n%G + CO
__global__ __launch_bounds__(256) void gemm_mma(
    const __nv_bfloat16* __restrict__ A, const __nv_bfloat16* __restrict__ B,
    const float* __restrict__ bias, float* __restrict__ C,
    int K, int row_stride, int G, int GS, int CO)
{
    extern __shared__ __align__(1024) char sm[];
    const uint32_t sbase = smem_u32(sm);
    const int tid = threadIdx.x;
    const int wid = tid >> 5, L = tid & 31;
    const int wm = wid >> 2, wn = wid & 3;
    const int bm = blockIdx.y * 128, bn = blockIdx.x * 128;
    const size_t rowb = (size_t)K * 2;
    const char* gA = (const char*)A + (size_t)bm * rowb;
    const char* gB = (const char*)B + (size_t)bn * rowb;

    // per-thread cp.async unit coords (two units per operand per stage)
    const int u0 = tid, u1 = tid + 256;
    const int r0 = u0 >> 2, c0 = u0 & 3;
    const int r1 = u1 >> 2, c1 = u1 & 3;
    const uint32_t d0 = (uint32_t)(r0 * 64 + ((c0 ^ ((r0 >> 1) & 3)) * 16));
    const uint32_t d1 = (uint32_t)(r1 * 64 + ((c1 ^ ((r1 >> 1) & 3)) * 16));
    const size_t s0A = (size_t)r0 * rowb + c0 * 16;
    const size_t s1A = (size_t)r1 * rowb + c1 * 16;

    const int NC = K >> 5;

#define LOAD_STAGE(st) do {                                              \
        const int _s = (st) & 3;                                         \
        const int _k0 = (st) << 5;                                       \
        const uint32_t aB = sbase + _s * STAGE_BYTES;                    \
        const uint32_t bB = sbase + NSTAGE * STAGE_BYTES + _s * STAGE_BYTES; \
        CP_ASYNC16(aB + d0, gA + s0A + _k0 * 2);                         \
        CP_ASYNC16(aB + d1, gA + s1A + _k0 * 2);                         \
        CP_ASYNC16(bB + d0, gB + s0A + _k0 * 2);                         \
        CP_ASYNC16(bB + d1, gB + s1A + _k0 * 2);                         \
    } while (0)

    // preload stages 0..2
    LOAD_STAGE(0); CP_COMMIT();
    LOAD_STAGE(1); CP_COMMIT();
    LOAD_STAGE(2); CP_COMMIT();

    float acc[4][4][4];
#pragma unroll
    for (int mi = 0; mi < 4; mi++)
#pragma unroll
        for (int ni = 0; ni < 4; ni++)
#pragma unroll
            for (int f = 0; f < 4; f++) acc[mi][ni][f] = 0.f;

    // ldmatrix per-thread base coords
    const int lr = L & 15;          // row within 16-row tile
    const int lku = L >> 4;         // k half (16B unit offset)

    for (int i = 0; i < NC; i++) {
        CP_WAIT2();
        __syncthreads();
        if (i + 3 < NC) LOAD_STAGE(i + 3);
        CP_COMMIT();

        const int buf = i & 3;
        const uint32_t aB = sbase + buf * STAGE_BYTES;
        const uint32_t bB = sbase + NSTAGE * STAGE_BYTES + buf * STAGE_BYTES;
#pragma unroll
        for (int ks = 0; ks < 2; ks++) {
            const int c16 = ks * 2 + lku;
            uint32_t afr[4][4], bfr[2][4];
#pragma unroll
            for (int mi = 0; mi < 4; mi++) {
                const int r = wm * 64 + mi * 16 + lr;
                ldsm4(afr[mi], aB + r * 64 + ((c16 ^ ((r >> 1) & 3)) * 16));
            }
#pragma unroll
            for (int nj = 0; nj < 2; nj++) {
                const int r = wn * 32 + nj * 16 + lr;
                ldsm4(bfr[nj], bB + r * 64 + ((c16 ^ ((r >> 1) & 3)) * 16));
            }
#pragma unroll
            for (int mi = 0; mi < 4; mi++)
#pragma unroll
                for (int ni = 0; ni < 4; ni++)
                    mma16816(acc[mi][ni], afr[mi],
                             bfr[ni >> 1][ni & 1], bfr[ni >> 1][(ni & 1) + 2]);
        }
        __syncthreads();
    }
#undef LOAD_STAGE

    // epilogue: bias + head-scatter
    const int g = L >> 2, tg = L & 3;
#pragma unroll
    for (int mi = 0; mi < 4; mi++) {
#pragma unroll
        for (int ni = 0; ni < 4; ni++) {
            const int n = bn + wn * 32 + ni * 8 + 2 * tg;
            const float b0 = bias[n], b1 = bias[n + 1];
            const size_t ncol = (size_t)(n / G) * GS + (n % G) + CO;
            const int mlo = bm + wm * 64 + mi * 16 + g;
            float2 v0 = make_float2(acc[mi][ni][0] + b0, acc[mi][ni][1] + b1);
            float2 v1 = make_float2(acc[mi][ni][2] + b0, acc[mi][ni][3] + b1);
            *(float2*)(C + (size_t)mlo * row_stride + ncol) = v0;
            *(float2*)(C + (size_t)(mlo + 8) * row_stride + ncol) = v1;
        }
    }
}

// ---------------- fp32 -> bf16 hi/lo split+concat --------------------------
// dst[M, 3K]: seg0 = hi; seg1 = modeA?lo:hi; seg2 = modeA?hi:lo
__global__ void split3(const float* __restrict__ src, __nv_bfloat16* __restrict__ dst,
                       int K, int total2, int modeA)
{
    int idx = blockIdx.x * blockDim.x + threadIdx.x;
    if (idx >= total2) return;
    const int k2 = K >> 1;
    const int row = idx / k2;
    const int kk = (idx - row * k2) * 2;
    float2 v = *(const float2*)(src + (size_t)row * K + kk);
    __nv_bfloat16 h0 = __float2bfloat16(v.x), h1 = __float2bfloat16(v.y);
    __nv_bfloat16 l0 = __float2bfloat16(v.x - __bfloat162float(h0));
    __nv_bfloat16 l1 = __float2bfloat16(v.y - __bfloat162float(h1));
    __nv_bfloat162 hh = __halves2bfloat162(h0, h1);
    __nv_bfloat162 ll = __halves2bfloat162(l0, l1);
    size_t base = (size_t)row * 3 * K + kk;
    *(__nv_bfloat162*)(dst + base)         = hh;
    *(__nv_bfloat162*)(dst + base + K)     = modeA ? ll : hh;
    *(__nv_bfloat162*)(dst + base + 2 * K) = modeA ? hh : ll;
}

// ---------------- RoPE (positions = head index, per reference) -------------
__global__ void rope_kernel(const float* __restrict__ raw, float* __restrict__ dst)
{
    int idx = blockIdx.x * blockDim.x + threadIdx.x;
    if (idx >= S_LEN * NHEAD * (RDIM / 2)) return;
    int i = idx & 31;
    int h = (idx >> 5) & 15;
    int s = idx >> 9;
    size_t rb = (size_t)s * (NHEAD * RDIM) + h * RDIM + 2 * i;
    float x1 = raw[rb], x2 = raw[rb + 1];
    float inv_freq = powf(10000.f, -((float)(2 * i)) / (float)RDIM);
    float ang = (float)h * inv_freq;
    float sv, cv;
    sincosf(ang, &sv, &cv);
    size_t ob = (size_t)s * KROW + h * DTOT + HDIM + 2 * i;
    dst[ob]     = x1 * cv - x2 * sv;
    dst[ob + 1] = x1 * sv + x2 * cv;
}

// ---------------- fused flash attention (fp32, unchanged) ------------------
#define QPAD 193
#define SPAD 65
#define ATTN_SMEM_FLOATS (64*QPAD*2 + 64*128 + 64*SPAD + 3*64)
#define ATTN_SMEM_BYTES  (ATTN_SMEM_FLOATS * 4)

__global__ __launch_bounds__(256) void attn_kernel(
    const float* __restrict__ Qg, const float* __restrict__ Kg,
    const float* __restrict__ Vg, float* __restrict__ Og)
{
    extern __shared__ float smf[];
    float* Qs    = smf;
    float* Ks    = Qs + 64 * QPAD;
    float* Vs    = Ks + 64 * QPAD;
    float* Ss    = Vs + 64 * 128;
    float* row_m = Ss + 64 * SPAD;
    float* row_l = row_m + 64;
    float* row_c = row_l + 64;

    const int tid = threadIdx.x;
    const int tx = tid & 15, ty = tid >> 4;
    const int h = blockIdx.y;
    const int q0 = blockIdx.x * 64;
    const float scale = 1.f / sqrtf((float)DTOT);

    for (int idx = tid; idx < 64 * 48; idx += 256) {
        int r = idx / 48, c4 = (idx % 48) * 4;
        float4 v = *(const float4*)(Qg + (size_t)(q0 + r) * KROW + h * DTOT + c4);
        float* p = &Qs[r * QPAD + c4];
        p[0] = v.x; p[1] = v.y; p[2] = v.z; p[3] = v.w;
    }
    if (tid < 64) { row_m[tid] = -INFINITY; row_l[tid] = 0.f; }

    float acc[4][8];
#pragma unroll
    for (int i = 0; i < 4; i++)
#pragma unroll
        for (int j = 0; j < 8; j++) acc[i][j] = 0.f;

    for (int t = 0; t < S_LEN / 64; t++) {
        const int k0 = t * 64;
        __syncthreads();
        for (int idx = tid; idx < 64 * 48; idx += 256) {
            int r = idx / 48, c4 = (idx % 48) * 4;
            float4 v = *(const float4*)(Kg + (size_t)(k0 + r) * KROW + h * DTOT + c4);
            float* p = &Ks[r * QPAD + c4];
            p[0] = v.x; p[1] = v.y; p[2] = v.z; p[3] = v.w;
        }
        for (int idx = tid; idx < 64 * 32; idx += 256) {
            int r = idx / 32, c4 = (idx % 32) * 4;
            float4 v = *(const float4*)(Vg + (size_t)(k0 + r) * VROW + h * HDIM + c4);
            *(float4*)&Vs[r * 128 + c4] = v;
        }
        __syncthreads();

        float s4[4][4];
#pragma unroll
        for (int i = 0; i < 4; i++)
#pragma unroll
            for (int j = 0; j < 4; j++) s4[i][j] = 0.f;
#pragma unroll 4
        for (int d = 0; d < DTOT; d++) {
            float ar[4], br[4];
#pragma unroll
            for (int i = 0; i < 4; i++) ar[i] = Qs[(ty * 4 + i) * QPAD + d];
#pragma unroll
            for (int j = 0; j < 4; j++) br[j] = Ks[(tx * 4 + j) * QPAD + d];
#pragma unroll
            for (int i = 0; i < 4; i++)
#pragma unroll
                for (int j = 0; j < 4; j++)
                    s4[i][j] += ar[i] * br[j];
        }
#pragma unroll
        for (int i = 0; i < 4; i++)
#pragma unroll
            for (int j = 0; j < 4; j++)
                Ss[(ty * 4 + i) * SPAD + tx * 4 + j] = s4[i][j] * scale;
        __syncthreads();

        {
            int r = tid >> 2, q = tid & 3;
            float mloc = -INFINITY;
            const float* srow = &Ss[r * SPAD + q * 16];
#pragma unroll
            for (int c = 0; c < 16; c++) mloc = fmaxf(mloc, srow[c]);
            mloc = fmaxf(mloc, __shfl_xor_sync(0xffffffffu, mloc, 1));
            mloc = fmaxf(mloc, __shfl_xor_sync(0xffffffffu, mloc, 2));
            float m_old = row_m[r];
            float m_new = fmaxf(m_old, mloc);
            float lsum = 0.f;
            float* swrow = &Ss[r * SPAD + q * 16];
#pragma unroll
            for (int c = 0; c < 16; c++) {
                float p = __expf(swrow[c] - m_new);
                swrow[c] = p;
                lsum += p;
            }
            lsum += __shfl_xor_sync(0xffffffffu, lsum, 1);
            lsum += __shfl_xor_sync(0xffffffffu, lsum, 2);
            if (q == 0) {
                row_c[r] = __expf(m_old - m_new);
                row_m[r] = m_new;
                row_l[r] = row_l[r] * row_c[r] + lsum;
            }
        }
        __syncthreads();

        float cr[4];
#pragma unroll
        for (int i = 0; i < 4; i++) cr[i] = row_c[ty * 4 + i];
#pragma unroll
        for (int i = 0; i < 4; i++)
#pragma unroll
            for (int j = 0; j < 8; j++) acc[i][j] *= cr[i];

#pragma unroll 4
        for (int k = 0; k < 64; k++) {
            float p[4], v[8];
#pragma unroll
            for (int i = 0; i < 4; i++) p[i] = Ss[(ty * 4 + i) * SPAD + k];
            *(float4*)&v[0] = *(const float4*)&Vs[k * 128 + tx * 8];
            *(float4*)&v[4] = *(const float4*)&Vs[k * 128 + tx * 8 + 4];
#pragma unroll
            for (int i = 0; i < 4; i++)
#pragma unroll
                for (int j = 0; j < 8; j++)
                    acc[i][j] += p[i] * v[j];
        }
    }
    __syncthreads();

    float inv_l[4];
#pragma unroll
    for (int i = 0; i < 4; i++) inv_l[i] = 1.f / row_l[ty * 4 + i];
#pragma unroll
    for (int i = 0; i < 4; i++) {
        int r = q0 + ty * 4 + i;
#pragma unroll
        for (int j = 0; j < 8; j += 4) {
            float4 o;
            o.x = acc[i][j + 0] * inv_l[i];
            o.y = acc[i][j + 1] * inv_l[i];
            o.z = acc[i][j + 2] * inv_l[i];
            o.w = acc[i][j + 3] * inv_l[i];
            *(float4*)(Og + (size_t)r * VROW + h * HDIM + tx * 8 + j) = o;
        }
    }
}

// ---------------- launcher -------------------------------------------------
static inline void launch_split(const float* src, __nv_bfloat16* dst, int M, int K, int modeA)
{
    int total2 = (M * K) >> 1;
    split3<<<(total2 + 255) / 256, 256>>>(src, dst, K, total2, modeA);
}

extern "C" void kernel_launch(void* const* d_in, const int* in_sizes, int n_in,
                              void* d_out, int out_size)
{
    const float* x            = (const float*)d_in[0];
    const float* kv_down_w    = (const float*)d_in[1];
    const float* kv_down_b    = (const float*)d_in[2];
    const float* key_up_w     = (const float*)d_in[3];
    const float* key_up_b     = (const float*)d_in[4];
    const float* value_up_w   = (const float*)d_in[5];
    const float* value_up_b   = (const float*)d_in[6];
    const float* key_rope_w   = (const float*)d_in[7];
    const float* key_rope_b   = (const float*)d_in[8];
    const float* query_down_w = (const float*)d_in[9];
    const float* query_down_b = (const float*)d_in[10];
    const float* query_up_w   = (const float*)d_in[11];
    const float* query_up_b   = (const float*)d_in[12];
    const float* query_rope_w = (const float*)d_in[13];
    const float* query_rope_b = (const float*)d_in[14];
    const float* out_w        = (const float*)d_in[15];
    const float* out_b        = (const float*)d_in[16];
    float* out = (float*)d_out;

    float *kv_c, *q_c, *keys, *queries, *values, *rraw, *ctx;
    cudaGetSymbolAddress((void**)&kv_c,    g_kv_c);
    cudaGetSymbolAddress((void**)&q_c,     g_q_c);
    cudaGetSymbolAddress((void**)&keys,    g_keys);
    cudaGetSymbolAddress((void**)&queries, g_queries);
    cudaGetSymbolAddress((void**)&values,  g_values);
    cudaGetSymbolAddress((void**)&rraw,    g_rope_raw);
    cudaGetSymbolAddress((void**)&ctx,     g_ctx);

    __nv_bfloat16 *x2, *kvc2, *qc2, *ctx2, *wkvd, *wqd, *wku, *wvu, *wkr, *wqu, *wqr, *wout;
    cudaGetSymbolAddress((void**)&x2,   g_x2);
    cudaGetSymbolAddress((void**)&kvc2, g_kvc2);
    cudaGetSymbolAddress((void**)&qc2,  g_qc2);
    cudaGetSymbolAddress((void**)&ctx2, g_ctx2);
    cudaGetSymbolAddress((void**)&wkvd, g_w_kvd);
    cudaGetSymbolAddress((void**)&wqd,  g_w_qd);
    cudaGetSymbolAddress((void**)&wku,  g_w_ku);
    cudaGetSymbolAddress((void**)&wvu,  g_w_vu);
    cudaGetSymbolAddress((void**)&wkr,  g_w_kr);
    cudaGetSymbolAddress((void**)&wqu,  g_w_qu);
    cudaGetSymbolAddress((void**)&wqr,  g_w_qr);
    cudaGetSymbolAddress((void**)&wout, g_w_out);

    cudaFuncSetAttribute(gemm_mma, cudaFuncAttributeMaxDynamicSharedMemorySize, GEMM_SMEM_BYTES);
    cudaFuncSetAttribute(attn_kernel, cudaFuncAttributeMaxDynamicSharedMemorySize, ATTN_SMEM_BYTES);

    // ---- operand conversion (stage 1) ----
    launch_split(x,            x2,   S_LEN, HIDDEN, 1);
    launch_split(kv_down_w,    wkvd, KVC,   HIDDEN, 0);
    launch_split(query_down_w, wqd,  QC,    HIDDEN, 0);

    // ---- down projections ----
    gemm_mma<<<dim3(KVC / 128, S_LEN / 128), 256, GEMM_SMEM_BYTES>>>(
        x2, wkvd, kv_down_b, kv_c, 3 * HIDDEN, KVC, KVC, 0, 0);
    gemm_mma<<<dim3(QC / 128, S_LEN / 128), 256, GEMM_SMEM_BYTES>>>(
        x2, wqd, query_down_b, q_c, 3 * HIDDEN, QC, QC, 0, 0);

    // ---- operand conversion (stage 2) ----
    launch_split(kv_c,         kvc2, S_LEN, KVC, 1);
    launch_split(q_c,          qc2,  S_LEN, QC,  1);
    launch_split(key_up_w,     wku,  VROW,  KVC, 0);
    launch_split(value_up_w,   wvu,  VROW,  KVC, 0);
    launch_split(key_rope_w,   wkr,  NHEAD * RDIM, KVC, 0);
    launch_split(query_up_w,   wqu,  VROW,  QC, 0);
    launch_split(query_rope_w, wqr,  NHEAD * RDIM, QC, 0);

    // ---- up projections ----
    gemm_mma<<<dim3(VROW / 128, S_LEN / 128), 256, GEMM_SMEM_BYTES>>>(
        kvc2, wku, key_up_b, keys, 3 * KVC, KROW, HDIM, DTOT, 0);
    gemm_mma<<<dim3(VROW / 128, S_LEN / 128), 256, GEMM_SMEM_BYTES>>>(
        kvc2, wvu, value_up_b, values, 3 * KVC, VROW, VROW, 0, 0);
    gemm_mma<<<dim3((NHEAD * RDIM) / 128, S_LEN / 128), 256, GEMM_SMEM_BYTES>>>(
        kvc2, wkr, key_rope_b, rraw, 3 * KVC, NHEAD * RDIM, NHEAD * RDIM, 0, 0);
    {
        int n = S_LEN * NHEAD * (RDIM / 2);
        rope_kernel<<<(n + 255) / 256, 256>>>(rraw, keys);
    }
    gemm_mma<<<dim3(VROW / 128, S_LEN / 128), 256, GEMM_SMEM_BYTES>>>(
        qc2, wqu, query_up_b, queries, 3 * QC, KROW, HDIM, DTOT, 0);
    gemm_mma<<<dim3((NHEAD * RDIM) / 128, S_LEN / 128), 256, GEMM_SMEM_BYTES>>>(
        qc2, wqr, query_rope_b, rraw, 3 * QC, NHEAD * RDIM, NHEAD * RDIM, 0, 0);
    {
        int n = S_LEN * NHEAD * (RDIM / 2);
        rope_kernel<<<(n + 255) / 256, 256>>>(rraw, queries);
    }

    // ---- attention (fp32) ----
    attn_kernel<<<dim3(S_LEN / 64, NHEAD), 256, ATTN_SMEM_BYTES>>>(
        queries, keys, values, ctx);

    // ---- output projection ----
    launch_split(ctx,   ctx2, S_LEN,  VROW, 1);
    launch_split(out_w, wout, HIDDEN, VROW, 0);
    gemm_mma<<<dim3(HIDDEN / 128, S_LEN / 128), 256, GEMM_SMEM_BYTES>>>(
        ctx2, wout, out_b, out, 3 * VROW, HIDDEN, HIDDEN, 0, 0);
}

// round 11
// speedup vs baseline: 2.6397x; 1.8258x over previous
#include <cuda_runtime.h>
#include <cuda_bf16.h>
#include <math.h>
#include <stdint.h>

#define S_LEN 2048
#define HIDDEN 2048
#define NHEAD 16
#define HDIM 128
#define RDIM 64
#define KVC 512
#define QC 1024
#define DTOT 192           // HDIM + RDIM
#define KROW (NHEAD*DTOT)  // 3072
#define VROW (NHEAD*HDIM)  // 2048

// ---------------- fp32 scratch ---------------------------------------------
__device__ float g_kv_c[S_LEN * KVC];
__device__ float g_q_c[S_LEN * QC];
__device__ float g_keys[S_LEN * KROW];
__device__ float g_queries[S_LEN * KROW];
__device__ float g_values[S_LEN * VROW];
__device__ float g_rope_raw[S_LEN * NHEAD * RDIM];
__device__ float g_ctx[S_LEN * VROW];

// ---------------- bf16x3 operand scratch -----------------------------------
__device__ __align__(1024) __nv_bfloat16 g_x2   [S_LEN * 3 * HIDDEN];
__device__ __align__(1024) __nv_bfloat16 g_kvc2 [S_LEN * 3 * KVC];
__device__ __align__(1024) __nv_bfloat16 g_qc2  [S_LEN * 3 * QC];
__device__ __align__(1024) __nv_bfloat16 g_ctx2 [S_LEN * 3 * VROW];
__device__ __align__(1024) __nv_bfloat16 g_w_kvd[KVC * 3 * HIDDEN];
__device__ __align__(1024) __nv_bfloat16 g_w_qd [QC * 3 * HIDDEN];
__device__ __align__(1024) __nv_bfloat16 g_w_ku [VROW * 3 * KVC];
__device__ __align__(1024) __nv_bfloat16 g_w_vu [VROW * 3 * KVC];
__device__ __align__(1024) __nv_bfloat16 g_w_kr [(NHEAD*RDIM) * 3 * KVC];
__device__ __align__(1024) __nv_bfloat16 g_w_qu [VROW * 3 * QC];
__device__ __align__(1024) __nv_bfloat16 g_w_qr [(NHEAD*RDIM) * 3 * QC];
__device__ __align__(1024) __nv_bfloat16 g_w_out[HIDDEN * 3 * VROW];

// ---------------- per-head bf16 attention operands -------------------------
__device__ __align__(1024) __nv_bfloat16 g_qbf [NHEAD * S_LEN * DTOT];
__device__ __align__(1024) __nv_bfloat16 g_kbf [NHEAD * S_LEN * DTOT];
__device__ __align__(1024) __nv_bfloat16 g_vbf [NHEAD * S_LEN * HDIM];   // hi
__device__ __align__(1024) __nv_bfloat16 g_vbfl[NHEAD * S_LEN * HDIM];   // lo

// ---------------- mma.sync helpers (sm_80 baseline PTX) --------------------
__device__ __forceinline__ uint32_t smem_u32(const void* p) {
    uint32_t a;
    asm("{ .reg .u64 t; cvta.to.shared.u64 t, %1; cvt.u32.u64 %0, t; }" : "=r"(a) : "l"(p));
    return a;
}
__device__ __forceinline__ uint32_t bf2_as_u32(__nv_bfloat162 v) {
    return *reinterpret_cast<uint32_t*>(&v);
}
__device__ __forceinline__ void ldsm4(uint32_t* r, uint32_t addr) {
    asm volatile("ldmatrix.sync.aligned.m8n8.x4.shared.b16 {%0,%1,%2,%3}, [%4];"
                 : "=r"(r[0]), "=r"(r[1]), "=r"(r[2]), "=r"(r[3]) : "r"(addr));
}
__device__ __forceinline__ void ldsm4t(uint32_t* r, uint32_t addr) {
    asm volatile("ldmatrix.sync.aligned.m8n8.x4.trans.shared.b16 {%0,%1,%2,%3}, [%4];"
                 : "=r"(r[0]), "=r"(r[1]), "=r"(r[2]), "=r"(r[3]) : "r"(addr));
}
__device__ __forceinline__ void mma16816(float* d, const uint32_t* a, uint32_t b0, uint32_t b1) {
    asm volatile("mma.sync.aligned.m16n8k16.row.col.f32.bf16.bf16.f32 "
                 "{%0,%1,%2,%3}, {%4,%5,%6,%7}, {%8,%9}, {%0,%1,%2,%3};"
                 : "+f"(d[0]), "+f"(d[1]), "+f"(d[2]), "+f"(d[3])
                 : "r"(a[0]), "r"(a[1]), "r"(a[2]), "r"(a[3]), "r"(b0), "r"(b1));
}
#define CP_ASYNC16(dst, src) \
    asm volatile("cp.async.cg.shared.global [%0], [%1], 16;" :: "r"(dst), "l"(src))
#define CP_COMMIT() asm volatile("cp.async.commit_group;" ::: "memory")
#define CP_WAIT2()  asm volatile("cp.async.wait_group 2;" ::: "memory")
#define CP_WAIT1()  asm volatile("cp.async.wait_group 1;" ::: "memory")

// ================= mma.sync NT GEMM (unchanged from R4) ====================
#define NSTAGE 4
#define STAGE_BYTES 8192
#define GEMM_SMEM_BYTES (NSTAGE * STAGE_BYTES * 2)   // 65536

__global__ __launch_bounds__(256) void gemm_mma(
    const __nv_bfloat16* __restrict__ A, const __nv_bfloat16* __restrict__ B,
    const float* __restrict__ bias, float* __restrict__ C,
    int K, int row_stride, int G, int GS, int CO)
{
    extern __shared__ __align__(1024) char sm[];
    const uint32_t sbase = smem_u32(sm);
    const int tid = threadIdx.x;
    const int wid = tid >> 5, L = tid & 31;
    const int wm = wid >> 2, wn = wid & 3;
    const int bm = blockIdx.y * 128, bn = blockIdx.x * 128;
    const size_t rowb = (size_t)K * 2;
    const char* gA = (const char*)A + (size_t)bm * rowb;
    const char* gB = (const char*)B + (size_t)bn * rowb;

    const int u0 = tid, u1 = tid + 256;
    const int r0 = u0 >> 2, c0 = u0 & 3;
    const int r1 = u1 >> 2, c1 = u1 & 3;
    const uint32_t d0 = (uint32_t)(r0 * 64 + ((c0 ^ ((r0 >> 1) & 3)) * 16));
    const uint32_t d1 = (uint32_t)(r1 * 64 + ((c1 ^ ((r1 >> 1) & 3)) * 16));
    const size_t s0A = (size_t)r0 * rowb + c0 * 16;
    const size_t s1A = (size_t)r1 * rowb + c1 * 16;

    const int NC = K >> 5;

#define LOAD_STAGE(st) do {                                              \
        const int _s = (st) & 3;                                         \
        const int _k0 = (st) << 5;                                       \
        const uint32_t aB = sbase + _s * STAGE_BYTES;                    \
        const uint32_t bB = sbase + NSTAGE * STAGE_BYTES + _s * STAGE_BYTES; \
        CP_ASYNC16(aB + d0, gA + s0A + _k0 * 2);                         \
        CP_ASYNC16(aB + d1, gA + s1A + _k0 * 2);                         \
        CP_ASYNC16(bB + d0, gB + s0A + _k0 * 2);                         \
        CP_ASYNC16(bB + d1, gB + s1A + _k0 * 2);                         \
    } while (0)

    LOAD_STAGE(0); CP_COMMIT();
    LOAD_STAGE(1); CP_COMMIT();
    LOAD_STAGE(2); CP_COMMIT();

    float acc[4][4][4];
#pragma unroll
    for (int mi = 0; mi < 4; mi++)
#pragma unroll
        for (int ni = 0; ni < 4; ni++)
#pragma unroll
            for (int f = 0; f < 4; f++) acc[mi][ni][f] = 0.f;

    const int lr = L & 15;
    const int lku = L >> 4;

    for (int i = 0; i < NC; i++) {
        CP_WAIT2();
        __syncthreads();
        if (i + 3 < NC) LOAD_STAGE(i + 3);
        CP_COMMIT();

        const int buf = i & 3;
        const uint32_t aB = sbase + buf * STAGE_BYTES;
        const uint32_t bB = sbase + NSTAGE * STAGE_BYTES + buf * STAGE_BYTES;
#pragma unroll
        for (int ks = 0; ks < 2; ks++) {
            const int c16 = ks * 2 + lku;
            uint32_t afr[4][4], bfr[2][4];
#pragma unroll
            for (int mi = 0; mi < 4; mi++) {
                const int r = wm * 64 + mi * 16 + lr;
                ldsm4(afr[mi], aB + r * 64 + ((c16 ^ ((r >> 1) & 3)) * 16));
            }
#pragma unroll
            for (int nj = 0; nj < 2; nj++) {
                const int r = wn * 32 + nj * 16 + lr;
                ldsm4(bfr[nj], bB + r * 64 + ((c16 ^ ((r >> 1) & 3)) * 16));
            }
#pragma unroll
            for (int mi = 0; mi < 4; mi++)
#pragma unroll
                for (int ni = 0; ni < 4; ni++)
                    mma16816(acc[mi][ni], afr[mi],
                             bfr[ni >> 1][ni & 1], bfr[ni >> 1][(ni & 1) + 2]);
        }
        __syncthreads();
    }
#undef LOAD_STAGE

    const int g = L >> 2, tg = L & 3;
#pragma unroll
    for (int mi = 0; mi < 4; mi++) {
#pragma unroll
        for (int ni = 0; ni < 4; ni++) {
            const int n = bn + wn * 32 + ni * 8 + 2 * tg;
            const float b0 = bias[n], b1 = bias[n + 1];
            const size_t ncol = (size_t)(n / G) * GS + (n % G) + CO;
            const int mlo = bm + wm * 64 + mi * 16 + g;
            float2 v0 = make_float2(acc[mi][ni][0] + b0, acc[mi][ni][1] + b1);
            float2 v1 = make_float2(acc[mi][ni][2] + b0, acc[mi][ni][3] + b1);
            *(float2*)(C + (size_t)mlo * row_stride + ncol) = v0;
            *(float2*)(C + (size_t)(mlo + 8) * row_stride + ncol) = v1;
        }
    }
}

// ---------------- fp32 -> bf16 hi/lo split+concat --------------------------
__global__ void split3(const float* __restrict__ src, __nv_bfloat16* __restrict__ dst,
                       int K, int total2, int modeA)
{
    int idx = blockIdx.x * blockDim.x + threadIdx.x;
    if (idx >= total2) return;
    const int k2 = K >> 1;
    const int row = idx / k2;
    const int kk = (idx - row * k2) * 2;
    float2 v = *(const float2*)(src + (size_t)row * K + kk);
    __nv_bfloat16 h0 = __float2bfloat16(v.x), h1 = __float2bfloat16(v.y);
    __nv_bfloat16 l0 = __float2bfloat16(v.x - __bfloat162float(h0));
    __nv_bfloat16 l1 = __float2bfloat16(v.y - __bfloat162float(h1));
    __nv_bfloat162 hh = __halves2bfloat162(h0, h1);
    __nv_bfloat162 ll = __halves2bfloat162(l0, l1);
    size_t base = (size_t)row * 3 * K + kk;
    *(__nv_bfloat162*)(dst + base)         = hh;
    *(__nv_bfloat162*)(dst + base + K)     = modeA ? ll : hh;
    *(__nv_bfloat162*)(dst + base + 2 * K) = modeA ? hh : ll;
}

// ---------------- RoPE (positions = head index, per reference) -------------
__global__ void rope_kernel(const float* __restrict__ raw, float* __restrict__ dst)
{
    int idx = blockIdx.x * blockDim.x + threadIdx.x;
    if (idx >= S_LEN * NHEAD * (RDIM / 2)) return;
    int i = idx & 31;
    int h = (idx >> 5) & 15;
    int s = idx >> 9;
    size_t rb = (size_t)s * (NHEAD * RDIM) + h * RDIM + 2 * i;
    float x1 = raw[rb], x2 = raw[rb + 1];
    float inv_freq = powf(10000.f, -((float)(2 * i)) / (float)RDIM);
    float ang = (float)h * inv_freq;
    float sv, cv;
    sincosf(ang, &sv, &cv);
    size_t ob = (size_t)s * KROW + h * DTOT + HDIM + 2 * i;
    dst[ob]     = x1 * cv - x2 * sv;
    dst[ob + 1] = x1 * sv + x2 * cv;
}

// ---------------- head-gather fp32 -> bf16 convert -------------------------
// src [S][ROWW] (head h at offset h*D), dst [h][S][D] bf16
__global__ void conv_head(const float* __restrict__ src, __nv_bfloat16* __restrict__ dst,
                          int D, int ROWW, int total)
{
    int i = blockIdx.x * blockDim.x + threadIdx.x;
    if (i >= total) return;
    const int d2c = D >> 1;
    int d2 = i % d2c;
    int rem = i / d2c;
    int s = rem & (S_LEN - 1);
    int h = rem >> 11;
    float2 v = *(const float2*)(src + (size_t)s * ROWW + h * D + 2 * d2);
    *(__nv_bfloat162*)(dst + ((size_t)h * S_LEN + s) * D + 2 * d2) =
        __floats2bfloat162_rn(v.x, v.y);
}

// hi/lo variant for V (precision-critical PV path)
__global__ void conv_head_hl(const float* __restrict__ src,
                             __nv_bfloat16* __restrict__ dh, __nv_bfloat16* __restrict__ dl,
                             int D, int ROWW, int total)
{
    int i = blockIdx.x * blockDim.x + threadIdx.x;
    if (i >= total) return;
    const int d2c = D >> 1;
    int d2 = i % d2c;
    int rem = i / d2c;
    int s = rem & (S_LEN - 1);
    int h = rem >> 11;
    float2 v = *(const float2*)(src + (size_t)s * ROWW + h * D + 2 * d2);
    __nv_bfloat16 h0 = __float2bfloat16(v.x), h1 = __float2bfloat16(v.y);
    __nv_bfloat16 l0 = __float2bfloat16(v.x - __bfloat162float(h0));
    __nv_bfloat16 l1 = __float2bfloat16(v.y - __bfloat162float(h1));
    size_t off = ((size_t)h * S_LEN + s) * D + 2 * d2;
    *(__nv_bfloat162*)(dh + off) = __halves2bfloat162(h0, h1);
    *(__nv_bfloat162*)(dl + off) = __halves2bfloat162(l0, l1);
}

// ================= tensor-core flash attention =============================
// CTA: 128 q-rows x 1 head, 8 warps, k-tiles of 64, 2-stage cp.async.
// PV path compensated: O += Ph*Vh + Pl*Vh + Ph*Vl   (error ~ eps^2)
#define AT_QPITCH 400
#define AT_KPITCH 400
#define AT_VPITCH 272
#define AT_QS 0
#define AT_KS (128 * AT_QPITCH)                     // 51200
#define AT_VS (AT_KS + 2 * 64 * AT_KPITCH)          // 102400
#define AT_VLS (AT_VS + 2 * 64 * AT_VPITCH)         // 137216
#define AT_SMEM (AT_VLS + 2 * 64 * AT_VPITCH)       // 172032

__global__ __launch_bounds__(256) void attn_mma(
    const __nv_bfloat16* __restrict__ Qh, const __nv_bfloat16* __restrict__ Kh,
    const __nv_bfloat16* __restrict__ Vh, const __nv_bfloat16* __restrict__ Vl,
    float* __restrict__ ctx)
{
    extern __shared__ __align__(1024) char sm[];
    const uint32_t sb = smem_u32(sm);
    const int tid = threadIdx.x;
    const int wq = tid >> 5, L = tid & 31;
    const int g = L >> 2, tg = L & 3;
    const int h = blockIdx.y, q0 = blockIdx.x * 128;
    const char* Qg = (const char*)(Qh + ((size_t)h * S_LEN + q0) * DTOT);
    const char* Kg = (const char*)(Kh + (size_t)h * S_LEN * DTOT);
    const char* Vg = (const char*)(Vh + (size_t)h * S_LEN * HDIM);
    const char* Vlg = (const char*)(Vl + (size_t)h * S_LEN * HDIM);

    // Q load: 128 rows x 24 16B chunks (part of group 0)
#pragma unroll
    for (int c = tid; c < 128 * 24; c += 256) {
        int r = c / 24, cc = c - r * 24;
        CP_ASYNC16(sb + AT_QS + r * AT_QPITCH + cc * 16, Qg + (size_t)r * 384 + cc * 16);
    }

#define LOADKV(t, buf) do {                                                   \
        const int _kv = (t) * 64;                                             \
        const uint32_t _kB = sb + AT_KS + (buf) * 64 * AT_KPITCH;             \
        const uint32_t _vB = sb + AT_VS + (buf) * 64 * AT_VPITCH;             \
        const uint32_t _wB = sb + AT_VLS + (buf) * 64 * AT_VPITCH;            \
        for (int _c = tid; _c < 64 * 24; _c += 256) {                         \
            int _r = _c / 24, _cc = _c - _r * 24;                             \
            CP_ASYNC16(_kB + _r * AT_KPITCH + _cc * 16,                       \
                       Kg + (size_t)(_kv + _r) * 384 + _cc * 16);             \
        }                                                                     \
        for (int _c = tid; _c < 64 * 16; _c += 256) {                         \
            int _r = _c >> 4, _cc = _c & 15;                                  \
            CP_ASYNC16(_vB + _r * AT_VPITCH + _cc * 16,                       \
                       Vg + (size_t)(_kv + _r) * 256 + _cc * 16);             \
            CP_ASYNC16(_wB + _r * AT_VPITCH + _cc * 16,                       \
                       Vlg + (size_t)(_kv + _r) * 256 + _cc * 16);            \
        }                                                                     \
    } while (0)

    LOADKV(0, 0); CP_COMMIT();
    LOADKV(1, 1); CP_COMMIT();

    float ofr[16][4];
#pragma unroll
    for (int o = 0; o < 16; o++)
#pragma unroll
        for (int f = 0; f < 4; f++) ofr[o][f] = 0.f;
    float m0 = -INFINITY, m1 = -INFINITY, l0 = 0.f, l1 = 0.f;
    const float scale = rsqrtf((float)DTOT);

    // ldmatrix thread->address coords
    const int arow = (L & 7) + ((L >> 3) & 1) * 8;   // A-style (Q and V.trans)
    const int acol = ((L >> 4) & 1) * 8;             // halves
    const int brow = (L & 7) + ((L >> 4) & 1) * 8;   // B-style (K non-trans)
    const int bcol = ((L >> 3) & 1) * 8;

    for (int t = 0; t < S_LEN / 64; t++) {
        CP_WAIT1();
        __syncthreads();
        const int buf = t & 1;
        const uint32_t kB = sb + AT_KS + buf * 64 * AT_KPITCH;
        const uint32_t vB = sb + AT_VS + buf * 64 * AT_VPITCH;
        const uint32_t wB = sb + AT_VLS + buf * 64 * AT_VPITCH;

        // S = Q K^T : per-warp 16x64
        float sfr[8][4];
#pragma unroll
        for (int ni = 0; ni < 8; ni++)
#pragma unroll
            for (int f = 0; f < 4; f++) sfr[ni][f] = 0.f;
#pragma unroll
        for (int d0 = 0; d0 < DTOT; d0 += 16) {
            uint32_t a[4];
            ldsm4(a, sb + AT_QS + (wq * 16 + arow) * AT_QPITCH + (d0 + acol) * 2);
#pragma unroll
            for (int nk = 0; nk < 4; nk++) {
                uint32_t b[4];
                ldsm4(b, kB + (nk * 16 + brow) * AT_KPITCH + (d0 + bcol) * 2);
                mma16816(sfr[2 * nk], a, b[0], b[1]);
                mma16816(sfr[2 * nk + 1], a, b[2], b[3]);
            }
        }

        // online softmax (rows g, g+8 per thread; reduce across 4-lane groups)
        float mx0 = -INFINITY, mx1 = -INFINITY;
#pragma unroll
        for (int ni = 0; ni < 8; ni++) {
            mx0 = fmaxf(mx0, fmaxf(sfr[ni][0], sfr[ni][1]));
            mx1 = fmaxf(mx1, fmaxf(sfr[ni][2], sfr[ni][3]));
        }
        mx0 *= scale; mx1 *= scale;
        mx0 = fmaxf(mx0, __shfl_xor_sync(0xffffffffu, mx0, 1));
        mx0 = fmaxf(mx0, __shfl_xor_sync(0xffffffffu, mx0, 2));
        mx1 = fmaxf(mx1, __shfl_xor_sync(0xffffffffu, mx1, 1));
        mx1 = fmaxf(mx1, __shfl_xor_sync(0xffffffffu, mx1, 2));
        const float mn0 = fmaxf(m0, mx0), mn1 = fmaxf(m1, mx1);
        const float e0 = __expf(m0 - mn0), e1 = __expf(m1 - mn1);
        m0 = mn0; m1 = mn1;
        l0 *= e0; l1 *= e1;
#pragma unroll
        for (int o = 0; o < 16; o++) {
            ofr[o][0] *= e0; ofr[o][1] *= e0;
            ofr[o][2] *= e1; ofr[o][3] *= e1;
        }
        uint32_t pfh[8][2], pfl[8][2];
        float sum0 = 0.f, sum1 = 0.f;
#pragma unroll
        for (int ni = 0; ni < 8; ni++) {
            float p0 = __expf(sfr[ni][0] * scale - mn0);
            float p1 = __expf(sfr[ni][1] * scale - mn0);
            float p2 = __expf(sfr[ni][2] * scale - mn1);
            float p3 = __expf(sfr[ni][3] * scale - mn1);
            sum0 += p0 + p1; sum1 += p2 + p3;
            __nv_bfloat16 h0 = __float2bfloat16(p0), h1 = __float2bfloat16(p1);
            __nv_bfloat16 h2 = __float2bfloat16(p2), h3 = __float2bfloat16(p3);
            pfh[ni][0] = bf2_as_u32(__halves2bfloat162(h0, h1));
            pfh[ni][1] = bf2_as_u32(__halves2bfloat162(h2, h3));
            pfl[ni][0] = bf2_as_u32(__halves2bfloat162(
                __float2bfloat16(p0 - __bfloat162float(h0)),
                __float2bfloat16(p1 - __bfloat162float(h1))));
            pfl[ni][1] = bf2_as_u32(__halves2bfloat162(
                __float2bfloat16(p2 - __bfloat162float(h2)),
                __float2bfloat16(p3 - __bfloat162float(h3))));
        }
        l0 += sum0; l1 += sum1;

        // O += Ph Vh + Pl Vh + Ph Vl
#pragma unroll
        for (int kj = 0; kj < 4; kj++) {
            uint32_t ah[4] = { pfh[2 * kj][0], pfh[2 * kj][1],
                               pfh[2 * kj + 1][0], pfh[2 * kj + 1][1] };
            uint32_t al[4] = { pfl[2 * kj][0], pfl[2 * kj][1],
                               pfl[2 * kj + 1][0], pfl[2 * kj + 1][1] };
#pragma unroll
            for (int dt = 0; dt < 8; dt++) {
                uint32_t bh[4], bl[4];
                ldsm4t(bh, vB + (kj * 16 + arow) * AT_VPITCH + (dt * 16 + acol) * 2);
                ldsm4t(bl, wB + (kj * 16 + arow) * AT_VPITCH + (dt * 16 + acol) * 2);
                mma16816(ofr[2 * dt], ah, bh[0], bh[1]);
                mma16816(ofr[2 * dt + 1], ah, bh[2], bh[3]);
                mma16816(ofr[2 * dt], al, bh[0], bh[1]);
                mma16816(ofr[2 * dt + 1], al, bh[2], bh[3]);
                mma16816(ofr[2 * dt], ah, bl[0], bl[1]);
                mma16816(ofr[2 * dt + 1], ah, bl[2], bl[3]);
            }
        }

        __syncthreads();
        if (t + 2 < S_LEN / 64) LOADKV(t + 2, buf);
        CP_COMMIT();
    }
#undef LOADKV

    // epilogue: normalize + write
    float lt0 = l0 + __shfl_xor_sync(0xffffffffu, l0, 1);
    lt0 += __shfl_xor_sync(0xffffffffu, lt0, 2);
    float lt1 = l1 + __shfl_xor_sync(0xffffffffu, l1, 1);
    lt1 += __shfl_xor_sync(0xffffffffu, lt1, 2);
    const float inv0 = 1.f / lt0, inv1 = 1.f / lt1;
    const int r0 = q0 + wq * 16 + g, r1 = r0 + 8;
#pragma unroll
    for (int ni = 0; ni < 16; ni++) {
        const int col = h * HDIM + ni * 8 + 2 * tg;
        *(float2*)(ctx + (size_t)r0 * VROW + col) =
            make_float2(ofr[ni][0] * inv0, ofr[ni][1] * inv0);
        *(float2*)(ctx + (size_t)r1 * VROW + col) =
            make_float2(ofr[ni][2] * inv1, ofr[ni][3] * inv1);
    }
}

// ---------------- launcher -------------------------------------------------
static inline void launch_split(const float* src, __nv_bfloat16* dst, int M, int K, int modeA)
{
    int total2 = (M * K) >> 1;
    split3<<<(total2 + 255) / 256, 256>>>(src, dst, K, total2, modeA);
}

extern "C" void kernel_launch(void* const* d_in, const int* in_sizes, int n_in,
                              void* d_out, int out_size)
{
    const float* x            = (const float*)d_in[0];
    const float* kv_down_w    = (const float*)d_in[1];
    const float* kv_down_b    = (const float*)d_in[2];
    const float* key_up_w     = (const float*)d_in[3];
    const float* key_up_b     = (const float*)d_in[4];
    const float* value_up_w   = (const float*)d_in[5];
    const float* value_up_b   = (const float*)d_in[6];
    const float* key_rope_w   = (const float*)d_in[7];
    const float* key_rope_b   = (const float*)d_in[8];
    const float* query_down_w = (const float*)d_in[9];
    const float* query_down_b = (const float*)d_in[10];
    const float* query_up_w   = (const float*)d_in[11];
    const float* query_up_b   = (const float*)d_in[12];
    const float* query_rope_w = (const float*)d_in[13];
    const float* query_rope_b = (const float*)d_in[14];
    const float* out_w        = (const float*)d_in[15];
    const float* out_b        = (const float*)d_in[16];
    float* out = (float*)d_out;

    float *kv_c, *q_c, *keys, *queries, *values, *rraw, *ctx;
    cudaGetSymbolAddress((void**)&kv_c,    g_kv_c);
    cudaGetSymbolAddress((void**)&q_c,     g_q_c);
    cudaGetSymbolAddress((void**)&keys,    g_keys);
    cudaGetSymbolAddress((void**)&queries, g_queries);
    cudaGetSymbolAddress((void**)&values,  g_values);
    cudaGetSymbolAddress((void**)&rraw,    g_rope_raw);
    cudaGetSymbolAddress((void**)&ctx,     g_ctx);

    __nv_bfloat16 *x2, *kvc2, *qc2, *ctx2, *wkvd, *wqd, *wku, *wvu, *wkr, *wqu, *wqr, *wout;
    __nv_bfloat16 *qbf, *kbf, *vbf, *vbfl;
    cudaGetSymbolAddress((void**)&x2,   g_x2);
    cudaGetSymbolAddress((void**)&kvc2, g_kvc2);
    cudaGetSymbolAddress((void**)&qc2,  g_qc2);
    cudaGetSymbolAddress((void**)&ctx2, g_ctx2);
    cudaGetSymbolAddress((void**)&wkvd, g_w_kvd);
    cudaGetSymbolAddress((void**)&wqd,  g_w_qd);
    cudaGetSymbolAddress((void**)&wku,  g_w_ku);
    cudaGetSymbolAddress((void**)&wvu,  g_w_vu);
    cudaGetSymbolAddress((void**)&wkr,  g_w_kr);
    cudaGetSymbolAddress((void**)&wqu,  g_w_qu);
    cudaGetSymbolAddress((void**)&wqr,  g_w_qr);
    cudaGetSymbolAddress((void**)&wout, g_w_out);
    cudaGetSymbolAddress((void**)&qbf,  g_qbf);
    cudaGetSymbolAddress((void**)&kbf,  g_kbf);
    cudaGetSymbolAddress((void**)&vbf,  g_vbf);
    cudaGetSymbolAddress((void**)&vbfl, g_vbfl);

    cudaFuncSetAttribute(gemm_mma, cudaFuncAttributeMaxDynamicSharedMemorySize, GEMM_SMEM_BYTES);
    cudaFuncSetAttribute(attn_mma, cudaFuncAttributeMaxDynamicSharedMemorySize, AT_SMEM);

    // ---- operand conversion (stage 1) ----
    launch_split(x,            x2,   S_LEN, HIDDEN, 1);
    launch_split(kv_down_w,    wkvd, KVC,   HIDDEN, 0);
    launch_split(query_down_w, wqd,  QC,    HIDDEN, 0);

    // ---- down projections ----
    gemm_mma<<<dim3(KVC / 128, S_LEN / 128), 256, GEMM_SMEM_BYTES>>>(
        x2, wkvd, kv_down_b, kv_c, 3 * HIDDEN, KVC, KVC, 0, 0);
    gemm_mma<<<dim3(QC / 128, S_LEN / 128), 256, GEMM_SMEM_BYTES>>>(
        x2, wqd, query_down_b, q_c, 3 * HIDDEN, QC, QC, 0, 0);

    // ---- operand conversion (stage 2) ----
    launch_split(kv_c,         kvc2, S_LEN, KVC, 1);
    launch_split(q_c,          qc2,  S_LEN, QC,  1);
    launch_split(key_up_w,     wku,  VROW,  KVC, 0);
    launch_split(value_up_w,   wvu,  VROW,  KVC, 0);
    launch_split(key_rope_w,   wkr,  NHEAD * RDIM, KVC, 0);
    launch_split(query_up_w,   wqu,  VROW,  QC, 0);
    launch_split(query_rope_w, wqr,  NHEAD * RDIM, QC, 0);

    // ---- up projections ----
    gemm_mma<<<dim3(VROW / 128, S_LEN / 128), 256, GEMM_SMEM_BYTES>>>(
        kvc2, wku, key_up_b, keys, 3 * KVC, KROW, HDIM, DTOT, 0);
    gemm_mma<<<dim3(VROW / 128, S_LEN / 128), 256, GEMM_SMEM_BYTES>>>(
        kvc2, wvu, value_up_b, values, 3 * KVC, VROW, VROW, 0, 0);
    gemm_mma<<<dim3((NHEAD * RDIM) / 128, S_LEN / 128), 256, GEMM_SMEM_BYTES>>>(
        kvc2, wkr, key_rope_b, rraw, 3 * KVC, NHEAD * RDIM, NHEAD * RDIM, 0, 0);
    {
        int n = S_LEN * NHEAD * (RDIM / 2);
        rope_kernel<<<(n + 255) / 256, 256>>>(rraw, keys);
    }
    gemm_mma<<<dim3(VROW / 128, S_LEN / 128), 256, GEMM_SMEM_BYTES>>>(
        qc2, wqu, query_up_b, queries, 3 * QC, KROW, HDIM, DTOT, 0);
    gemm_mma<<<dim3((NHEAD * RDIM) / 128, S_LEN / 128), 256, GEMM_SMEM_BYTES>>>(
        qc2, wqr, query_rope_b, rraw, 3 * QC, NHEAD * RDIM, NHEAD * RDIM, 0, 0);
    {
        int n = S_LEN * NHEAD * (RDIM / 2);
        rope_kernel<<<(n + 255) / 256, 256>>>(rraw, queries);
    }

    // ---- per-head bf16 conversion ----
    {
        int tqk = NHEAD * S_LEN * (DTOT / 2);
        conv_head<<<(tqk + 255) / 256, 256>>>(queries, qbf, DTOT, KROW, tqk);
        conv_head<<<(tqk + 255) / 256, 256>>>(keys,    kbf, DTOT, KROW, tqk);
        int tv = NHEAD * S_LEN * (HDIM / 2);
        conv_head_hl<<<(tv + 255) / 256, 256>>>(values, vbf, vbfl, HDIM, VROW, tv);
    }

    // ---- tensor-core attention -> ctx ----
    attn_mma<<<dim3(S_LEN / 128, NHEAD), 256, AT_SMEM>>>(qbf, kbf, vbf, vbfl, ctx);

    // ---- output projection ----
    launch_split(ctx,   ctx2, S_LEN,  VROW, 1);
    launch_split(out_w, wout, HIDDEN, VROW, 0);
    gemm_mma<<<dim3(HIDDEN / 128, S_LEN / 128), 256, GEMM_SMEM_BYTES>>>(
        ctx2, wout, out_b, out, 3 * VROW, HIDDEN, HIDDEN, 0, 0);
}

// round 13
// speedup vs baseline: 4.7624x; 1.8041x over previous
#include <cuda_runtime.h>
#include <cuda_bf16.h>
#include <cuda_fp16.h>
#include <math.h>
#include <stdint.h>

#define S_LEN 2048
#define HIDDEN 2048
#define NHEAD 16
#define HDIM 128
#define RDIM 64
#define KVC 512
#define QC 1024
#define DTOT 192           // HDIM + RDIM
#define KROW (NHEAD*DTOT)  // 3072
#define VROW (NHEAD*HDIM)  // 2048

// ---------------- fp32 scratch ---------------------------------------------
__device__ float g_kv_c[S_LEN * KVC];
__device__ float g_q_c[S_LEN * QC];
__device__ float g_keys[S_LEN * KROW];
__device__ float g_queries[S_LEN * KROW];
__device__ float g_values[S_LEN * VROW];
__device__ float g_rope_raw[S_LEN * NHEAD * RDIM];
__device__ float g_ctx[S_LEN * VROW];

// ---------------- bf16x3 operand scratch (combined weight buffers) ---------
__device__ __align__(1024) __nv_bfloat16 g_x2    [S_LEN * 3 * HIDDEN];
__device__ __align__(1024) __nv_bfloat16 g_kvc2  [S_LEN * 3 * KVC];
__device__ __align__(1024) __nv_bfloat16 g_qc2   [S_LEN * 3 * QC];
__device__ __align__(1024) __nv_bfloat16 g_ctx2  [S_LEN * 3 * VROW];
__device__ __align__(1024) __nv_bfloat16 g_w_down[(KVC + QC) * 3 * HIDDEN];
__device__ __align__(1024) __nv_bfloat16 g_w_up  [(VROW + VROW + NHEAD*RDIM) * 3 * KVC];
__device__ __align__(1024) __nv_bfloat16 g_w_q   [(VROW + NHEAD*RDIM) * 3 * QC];
__device__ __align__(1024) __nv_bfloat16 g_w_out [HIDDEN * 3 * VROW];

// ---------------- per-head attention operands ------------------------------
__device__ __align__(1024) __nv_bfloat16 g_qbf[NHEAD * S_LEN * DTOT];
__device__ __align__(1024) __nv_bfloat16 g_kbf[NHEAD * S_LEN * DTOT];
__device__ __align__(1024) __half        g_vh [NHEAD * S_LEN * HDIM];

// ---------------- mma.sync helpers (sm_80 baseline PTX) --------------------
__device__ __forceinline__ uint32_t smem_u32(const void* p) {
    uint32_t a;
    asm("{ .reg .u64 t; cvta.to.shared.u64 t, %1; cvt.u32.u64 %0, t; }" : "=r"(a) : "l"(p));
    return a;
}
__device__ __forceinline__ uint32_t h2_as_u32(__half2 v) {
    return *reinterpret_cast<uint32_t*>(&v);
}
__device__ __forceinline__ void ldsm4(uint32_t* r, uint32_t addr) {
    asm volatile("ldmatrix.sync.aligned.m8n8.x4.shared.b16 {%0,%1,%2,%3}, [%4];"
                 : "=r"(r[0]), "=r"(r[1]), "=r"(r[2]), "=r"(r[3]) : "r"(addr));
}
__device__ __forceinline__ void ldsm4t(uint32_t* r, uint32_t addr) {
    asm volatile("ldmatrix.sync.aligned.m8n8.x4.trans.shared.b16 {%0,%1,%2,%3}, [%4];"
                 : "=r"(r[0]), "=r"(r[1]), "=r"(r[2]), "=r"(r[3]) : "r"(addr));
}
__device__ __forceinline__ void mma16816(float* d, const uint32_t* a, uint32_t b0, uint32_t b1) {
    asm volatile("mma.sync.aligned.m16n8k16.row.col.f32.bf16.bf16.f32 "
                 "{%0,%1,%2,%3}, {%4,%5,%6,%7}, {%8,%9}, {%0,%1,%2,%3};"
                 : "+f"(d[0]), "+f"(d[1]), "+f"(d[2]), "+f"(d[3])
                 : "r"(a[0]), "r"(a[1]), "r"(a[2]), "r"(a[3]), "r"(b0), "r"(b1));
}
__device__ __forceinline__ void mma16816h(float* d, const uint32_t* a, uint32_t b0, uint32_t b1) {
    asm volatile("mma.sync.aligned.m16n8k16.row.col.f32.f16.f16.f32 "
                 "{%0,%1,%2,%3}, {%4,%5,%6,%7}, {%8,%9}, {%0,%1,%2,%3};"
                 : "+f"(d[0]), "+f"(d[1]), "+f"(d[2]), "+f"(d[3])
                 : "r"(a[0]), "r"(a[1]), "r"(a[2]), "r"(a[3]), "r"(b0), "r"(b1));
}
#define CP_ASYNC16(dst, src) \
    asm volatile("cp.async.cg.shared.global [%0], [%1], 16;" :: "r"(dst), "l"(src))
#define CP_COMMIT() asm volatile("cp.async.commit_group;" ::: "memory")
#define CP_WAIT2()  asm volatile("cp.async.wait_group 2;" ::: "memory")
#define CP_WAIT1()  asm volatile("cp.async.wait_group 1;" ::: "memory")

// ================= segment-routed epilogue descriptor ======================
struct Seg { const float* bias; float* dst; int n0, rs, G, GS, CO; };
struct Epi3 { int nend0, nend1; Seg s0, s1, s2; };

// ================= mma.sync NT GEMM with fused epilogue ====================
#define NSTAGE 4
#define STAGE_BYTES 8192
#define GEMM_SMEM_BYTES (NSTAGE * STAGE_BYTES * 2)   // 65536

__global__ __launch_bounds__(256, 2) void gemm_mma(
    const __nv_bfloat16* __restrict__ A, const __nv_bfloat16* __restrict__ B,
    int K, Epi3 e)
{
    extern __shared__ __align__(1024) char sm[];
    const uint32_t sbase = smem_u32(sm);
    const int tid = threadIdx.x;
    const int wid = tid >> 5, L = tid & 31;
    const int wm = wid >> 2, wn = wid & 3;
    const int bm = blockIdx.y * 128, bn = blockIdx.x * 128;
    const size_t rowb = (size_t)K * 2;
    const char* gA = (const char*)A + (size_t)bm * rowb;
    const char* gB = (const char*)B + (size_t)bn * rowb;

    const int u0 = tid, u1 = tid + 256;
    const int r0 = u0 >> 2, c0 = u0 & 3;
    const int r1 = u1 >> 2, c1 = u1 & 3;
    const uint32_t d0 = (uint32_t)(r0 * 64 + ((c0 ^ ((r0 >> 1) & 3)) * 16));
    const uint32_t d1 = (uint32_t)(r1 * 64 + ((c1 ^ ((r1 >> 1) & 3)) * 16));
    const size_t s0A = (size_t)r0 * rowb + c0 * 16;
    const size_t s1A = (size_t)r1 * rowb + c1 * 16;

    const int NC = K >> 5;

#define LOAD_STAGE(st) do {                                              \
        const int _s = (st) & 3;                                         \
        const int _k0 = (st) << 5;                                       \
        const uint32_t aB = sbase + _s * STAGE_BYTES;                    \
        const uint32_t bB = sbase + NSTAGE * STAGE_BYTES + _s * STAGE_BYTES; \
        CP_ASYNC16(aB + d0, gA + s0A + _k0 * 2);                         \
        CP_ASYNC16(aB + d1, gA + s1A + _k0 * 2);                         \
        CP_ASYNC16(bB + d0, gB + s0A + _k0 * 2);                         \
        CP_ASYNC16(bB + d1, gB + s1A + _k0 * 2);                         \
    } while (0)

    LOAD_STAGE(0); CP_COMMIT();
    LOAD_STAGE(1); CP_COMMIT();
    LOAD_STAGE(2); CP_COMMIT();

    float acc[4][4][4];
#pragma unroll
    for (int mi = 0; mi < 4; mi++)
#pragma unroll
        for (int ni = 0; ni < 4; ni++)
#pragma unroll
            for (int f = 0; f < 4; f++) acc[mi][ni][f] = 0.f;

    const int lr = L & 15;
    const int lku = L >> 4;

    for (int i = 0; i < NC; i++) {
        CP_WAIT2();
        __syncthreads();
        if (i + 3 < NC) LOAD_STAGE(i + 3);
        CP_COMMIT();

        const int buf = i & 3;
        const uint32_t aB = sbase + buf * STAGE_BYTES;
        const uint32_t bB = sbase + NSTAGE * STAGE_BYTES + buf * STAGE_BYTES;
#pragma unroll
        for (int ks = 0; ks < 2; ks++) {
            const int c16 = ks * 2 + lku;
            uint32_t afr[4][4], bfr[2][4];
#pragma unroll
            for (int mi = 0; mi < 4; mi++) {
                const int r = wm * 64 + mi * 16 + lr;
                ldsm4(afr[mi], aB + r * 64 + ((c16 ^ ((r >> 1) & 3)) * 16));
            }
#pragma unroll
            for (int nj = 0; nj < 2; nj++) {
                const int r = wn * 32 + nj * 16 + lr;
                ldsm4(bfr[nj], bB + r * 64 + ((c16 ^ ((r >> 1) & 3)) * 16));
            }
#pragma unroll
            for (int mi = 0; mi < 4; mi++)
#pragma unroll
                for (int ni = 0; ni < 4; ni++)
                    mma16816(acc[mi][ni], afr[mi],
                             bfr[ni >> 1][ni & 1], bfr[ni >> 1][(ni & 1) + 2]);
        }
        __syncthreads();
    }
#undef LOAD_STAGE

    // epilogue: segment-routed bias + scatter (whole CTA tile in one segment)
    const Seg sg = (bn < e.nend0) ? e.s0 : (bn < e.nend1 ? e.s1 : e.s2);
    const int g = L >> 2, tg = L & 3;
#pragma unroll
    for (int mi = 0; mi < 4; mi++) {
#pragma unroll
        for (int ni = 0; ni < 4; ni++) {
            const int nl = bn + wn * 32 + ni * 8 + 2 * tg - sg.n0;
            const float b0 = sg.bias[nl], b1 = sg.bias[nl + 1];
            const size_t ncol = (size_t)(nl / sg.G) * sg.GS + (nl % sg.G) + sg.CO;
            const int mlo = bm + wm * 64 + mi * 16 + g;
            float2 v0 = make_float2(acc[mi][ni][0] + b0, acc[mi][ni][1] + b1);
            float2 v1 = make_float2(acc[mi][ni][2] + b0, acc[mi][ni][3] + b1);
            *(float2*)(sg.dst + (size_t)mlo * sg.rs + ncol) = v0;
            *(float2*)(sg.dst + (size_t)(mlo + 8) * sg.rs + ncol) = v1;
        }
    }
}

// ---------------- fp32 -> bf16 hi/lo split+concat --------------------------
__global__ void split3(const float* __restrict__ src, __nv_bfloat16* __restrict__ dst,
                       int K, int total2, int modeA)
{
    int idx = blockIdx.x * blockDim.x + threadIdx.x;
    if (idx >= total2) return;
    const int k2 = K >> 1;
    const int row = idx / k2;
    const int kk = (idx - row * k2) * 2;
    float2 v = *(const float2*)(src + (size_t)row * K + kk);
    __nv_bfloat16 h0 = __float2bfloat16(v.x), h1 = __float2bfloat16(v.y);
    __nv_bfloat16 l0 = __float2bfloat16(v.x - __bfloat162float(h0));
    __nv_bfloat16 l1 = __float2bfloat16(v.y - __bfloat162float(h1));
    __nv_bfloat162 hh = __halves2bfloat162(h0, h1);
    __nv_bfloat162 ll = __halves2bfloat162(l0, l1);
    size_t base = (size_t)row * 3 * K + kk;
    *(__nv_bfloat162*)(dst + base)         = hh;
    *(__nv_bfloat162*)(dst + base + K)     = modeA ? ll : hh;
    *(__nv_bfloat162*)(dst + base + 2 * K) = modeA ? hh : ll;
}

// ---------------- RoPE (positions = head index, per reference) -------------
__global__ void rope_kernel(const float* __restrict__ raw, float* __restrict__ dst)
{
    int idx = blockIdx.x * blockDim.x + threadIdx.x;
    if (idx >= S_LEN * NHEAD * (RDIM / 2)) return;
    int i = idx & 31;
    int h = (idx >> 5) & 15;
    int s = idx >> 9;
    size_t rb = (size_t)s * (NHEAD * RDIM) + h * RDIM + 2 * i;
    float x1 = raw[rb], x2 = raw[rb + 1];
    float inv_freq = powf(10000.f, -((float)(2 * i)) / (float)RDIM);
    float ang = (float)h * inv_freq;
    float sv, cv;
    sincosf(ang, &sv, &cv);
    size_t ob = (size_t)s * KROW + h * DTOT + HDIM + 2 * i;
    dst[ob]     = x1 * cv - x2 * sv;
    dst[ob + 1] = x1 * sv + x2 * cv;
}

// ---------------- head-gather converts -------------------------------------
// src [S][ROWW] (head h at offset h*D), dst [h][S][D]
__global__ void conv_head(const float* __restrict__ src, __nv_bfloat16* __restrict__ dst,
                          int D, int ROWW, int total)
{
    int i = blockIdx.x * blockDim.x + threadIdx.x;
    if (i >= total) return;
    const int d2c = D >> 1;
    int d2 = i % d2c;
    int rem = i / d2c;
    int s = rem & (S_LEN - 1);
    int h = rem >> 11;
    float2 v = *(const float2*)(src + (size_t)s * ROWW + h * D + 2 * d2);
    *(__nv_bfloat162*)(dst + ((size_t)h * S_LEN + s) * D + 2 * d2) =
        __floats2bfloat162_rn(v.x, v.y);
}

__global__ void conv_head_f16(const float* __restrict__ src, __half* __restrict__ dst,
                              int D, int ROWW, int total)
{
    int i = blockIdx.x * blockDim.x + threadIdx.x;
    if (i >= total) return;
    const int d2c = D >> 1;
    int d2 = i % d2c;
    int rem = i / d2c;
    int s = rem & (S_LEN - 1);
    int h = rem >> 11;
    float2 v = *(const float2*)(src + (size_t)s * ROWW + h * D + 2 * d2);
    *(__half2*)(dst + ((size_t)h * S_LEN + s) * D + 2 * d2) =
        __floats2half2_rn(v.x, v.y);
}

// ================= tensor-core flash attention =============================
// CTA: 128 q-rows x 1 head, 8 warps, k-tiles of 64, 2-stage cp.async.
// QK in bf16 (scores tiny -> error negligible); PV in fp16 (eps 8x smaller
// than bf16 -> predicted rel err ~2e-4, 5x under gate).
#define AT_QPITCH 400
#define AT_KPITCH 400
#define AT_VPITCH 272
#define AT_QS 0
#define AT_KS (128 * AT_QPITCH)                     // 51200
#define AT_VS (AT_KS + 2 * 64 * AT_KPITCH)          // 102400
#define AT_SMEM (AT_VS + 2 * 64 * AT_VPITCH)        // 137216

__global__ __launch_bounds__(256) void attn_mma(
    const __nv_bfloat16* __restrict__ Qh, const __nv_bfloat16* __restrict__ Kh,
    const __half* __restrict__ Vh, float* __restrict__ ctx)
{
    extern __shared__ __align__(1024) char sm[];
    const uint32_t sb = smem_u32(sm);
    const int tid = threadIdx.x;
    const int wq = tid >> 5, L = tid & 31;
    const int g = L >> 2, tg = L & 3;
    const int h = blockIdx.y, q0 = blockIdx.x * 128;
    const char* Qg = (const char*)(Qh + ((size_t)h * S_LEN + q0) * DTOT);
    const char* Kg = (const char*)(Kh + (size_t)h * S_LEN * DTOT);
    const char* Vg = (const char*)(Vh + (size_t)h * S_LEN * HDIM);

    // Q load: 128 rows x 24 16B chunks (part of group 0)
#pragma unroll
    for (int c = tid; c < 128 * 24; c += 256) {
        int r = c / 24, cc = c - r * 24;
        CP_ASYNC16(sb + AT_QS + r * AT_QPITCH + cc * 16, Qg + (size_t)r * 384 + cc * 16);
    }

#define LOADKV(t, buf) do {                                                   \
        const int _kv = (t) * 64;                                             \
        const uint32_t _kB = sb + AT_KS + (buf) * 64 * AT_KPITCH;             \
        const uint32_t _vB = sb + AT_VS + (buf) * 64 * AT_VPITCH;             \
        for (int _c = tid; _c < 64 * 24; _c += 256) {                         \
            int _r = _c / 24, _cc = _c - _r * 24;                             \
            CP_ASYNC16(_kB + _r * AT_KPITCH + _cc * 16,                       \
                       Kg + (size_t)(_kv + _r) * 384 + _cc * 16);             \
        }                                                                     \
        for (int _c = tid; _c < 64 * 16; _c += 256) {                         \
            int _r = _c >> 4, _cc = _c & 15;                                  \
            CP_ASYNC16(_vB + _r * AT_VPITCH + _cc * 16,                       \
                       Vg + (size_t)(_kv + _r) * 256 + _cc * 16);             \
        }                                                                     \
    } while (0)

    LOADKV(0, 0); CP_COMMIT();
    LOADKV(1, 1); CP_COMMIT();

    float ofr[16][4];
#pragma unroll
    for (int o = 0; o < 16; o++)
#pragma unroll
        for (int f = 0; f < 4; f++) ofr[o][f] = 0.f;
    float m0 = -INFINITY, m1 = -INFINITY, l0 = 0.f, l1 = 0.f;
    const float scale = rsqrtf((float)DTOT);

    // ldmatrix thread->address coords
    const int arow = (L & 7) + ((L >> 3) & 1) * 8;   // A-style (Q and V.trans)
    const int acol = ((L >> 4) & 1) * 8;             // halves
    const int brow = (L & 7) + ((L >> 4) & 1) * 8;   // B-style (K non-trans)
    const int bcol = ((L >> 3) & 1) * 8;

    for (int t = 0; t < S_LEN / 64; t++) {
        CP_WAIT1();
        __syncthreads();
        const int buf = t & 1;
        const uint32_t kB = sb + AT_KS + buf * 64 * AT_KPITCH;
        const uint32_t vB = sb + AT_VS + buf * 64 * AT_VPITCH;

        // S = Q K^T : per-warp 16x64
        float sfr[8][4];
#pragma unroll
        for (int ni = 0; ni < 8; ni++)
#pragma unroll
            for (int f = 0; f < 4; f++) sfr[ni][f] = 0.f;
#pragma unroll
        for (int d0 = 0; d0 < DTOT; d0 += 16) {
            uint32_t a[4];
            ldsm4(a, sb + AT_QS + (wq * 16 + arow) * AT_QPITCH + (d0 + acol) * 2);
#pragma unroll
            for (int nk = 0; nk < 4; nk++) {
                uint32_t b[4];
                ldsm4(b, kB + (nk * 16 + brow) * AT_KPITCH + (d0 + bcol) * 2);
                mma16816(sfr[2 * nk], a, b[0], b[1]);
                mma16816(sfr[2 * nk + 1], a, b[2], b[3]);
            }
        }

        // online softmax (rows g, g+8 per thread; reduce across 4-lane groups)
        float mx0 = -INFINITY, mx1 = -INFINITY;
#pragma unroll
        for (int ni = 0; ni < 8; ni++) {
            mx0 = fmaxf(mx0, fmaxf(sfr[ni][0], sfr[ni][1]));
            mx1 = fmaxf(mx1, fmaxf(sfr[ni][2], sfr[ni][3]));
        }
        mx0 *= scale; mx1 *= scale;
        mx0 = fmaxf(mx0, __shfl_xor_sync(0xffffffffu, mx0, 1));
        mx0 = fmaxf(mx0, __shfl_xor_sync(0xffffffffu, mx0, 2));
        mx1 = fmaxf(mx1, __shfl_xor_sync(0xffffffffu, mx1, 1));
        mx1 = fmaxf(mx1, __shfl_xor_sync(0xffffffffu, mx1, 2));
        const float mn0 = fmaxf(m0, mx0), mn1 = fmaxf(m1, mx1);
        const float e0 = __expf(m0 - mn0), e1 = __expf(m1 - mn1);
        m0 = mn0; m1 = mn1;
        l0 *= e0; l1 *= e1;
#pragma unroll
        for (int o = 0; o < 16; o++) {
            ofr[o][0] *= e0; ofr[o][1] *= e0;
            ofr[o][2] *= e1; ofr[o][3] *= e1;
        }
        uint32_t pfr[8][2];
        float sum0 = 0.f, sum1 = 0.f;
#pragma unroll
        for (int ni = 0; ni < 8; ni++) {
            float p0 = __expf(sfr[ni][0] * scale - mn0);
            float p1 = __expf(sfr[ni][1] * scale - mn0);
            float p2 = __expf(sfr[ni][2] * scale - mn1);
            float p3 = __expf(sfr[ni][3] * scale - mn1);
            sum0 += p0 + p1; sum1 += p2 + p3;
            pfr[ni][0] = h2_as_u32(__floats2half2_rn(p0, p1));
            pfr[ni][1] = h2_as_u32(__floats2half2_rn(p2, p3));
        }
        l0 += sum0; l1 += sum1;

        // O += P V (fp16 x fp16 -> fp32)
#pragma unroll
        for (int kj = 0; kj < 4; kj++) {
            uint32_t a[4] = { pfr[2 * kj][0], pfr[2 * kj][1],
                              pfr[2 * kj + 1][0], pfr[2 * kj + 1][1] };
#pragma unroll
            for (int dt = 0; dt < 8; dt++) {
                uint32_t b[4];
                ldsm4t(b, vB + (kj * 16 + arow) * AT_VPITCH + (dt * 16 + acol) * 2);
                mma16816h(ofr[2 * dt], a, b[0], b[1]);
                mma16816h(ofr[2 * dt + 1], a, b[2], b[3]);
            }
        }

        __syncthreads();
        if (t + 2 < S_LEN / 64) LOADKV(t + 2, buf);
        CP_COMMIT();
    }
#undef LOADKV

    // epilogue: normalize + write
    float lt0 = l0 + __shfl_xor_sync(0xffffffffu, l0, 1);
    lt0 += __shfl_xor_sync(0xffffffffu, lt0, 2);
    float lt1 = l1 + __shfl_xor_sync(0xffffffffu, l1, 1);
    lt1 += __shfl_xor_sync(0xffffffffu, lt1, 2);
    const float inv0 = 1.f / lt0, inv1 = 1.f / lt1;
    const int r0 = q0 + wq * 16 + g, r1 = r0 + 8;
#pragma unroll
    for (int ni = 0; ni < 16; ni++) {
        const int col = h * HDIM + ni * 8 + 2 * tg;
        *(float2*)(ctx + (size_t)r0 * VROW + col) =
            make_float2(ofr[ni][0] * inv0, ofr[ni][1] * inv0);
        *(float2*)(ctx + (size_t)r1 * VROW + col) =
            make_float2(ofr[ni][2] * inv1, ofr[ni][3] * inv1);
    }
}

// ---------------- launcher -------------------------------------------------
static inline void launch_split(const float* src, __nv_bfloat16* dst, int M, int K, int modeA)
{
    int total2 = (M * K) >> 1;
    split3<<<(total2 + 255) / 256, 256>>>(src, dst, K, total2, modeA);
}

extern "C" void kernel_launch(void* const* d_in, const int* in_sizes, int n_in,
                              void* d_out, int out_size)
{
    const float* x            = (const float*)d_in[0];
    const float* kv_down_w    = (const float*)d_in[1];
    const float* kv_down_b    = (const float*)d_in[2];
    const float* key_up_w     = (const float*)d_in[3];
    const float* key_up_b     = (const float*)d_in[4];
    const float* value_up_w   = (const float*)d_in[5];
    const float* value_up_b   = (const float*)d_in[6];
    const float* key_rope_w   = (const float*)d_in[7];
    const float* key_rope_b   = (const float*)d_in[8];
    const float* query_down_w = (const float*)d_in[9];
    const float* query_down_b = (const float*)d_in[10];
    const float* query_up_w   = (const float*)d_in[11];
    const float* query_up_b   = (const float*)d_in[12];
    const float* query_rope_w = (const float*)d_in[13];
    const float* query_rope_b = (const float*)d_in[14];
    const float* out_w        = (const float*)d_in[15];
    const float* out_b        = (const float*)d_in[16];
    float* out = (float*)d_out;

    float *kv_c, *q_c, *keys, *queries, *values, *rraw, *ctx;
    cudaGetSymbolAddress((void**)&kv_c,    g_kv_c);
    cudaGetSymbolAddress((void**)&q_c,     g_q_c);
    cudaGetSymbolAddress((void**)&keys,    g_keys);
    cudaGetSymbolAddress((void**)&queries, g_queries);
    cudaGetSymbolAddress((void**)&values,  g_values);
    cudaGetSymbolAddress((void**)&rraw,    g_rope_raw);
    cudaGetSymbolAddress((void**)&ctx,     g_ctx);

    __nv_bfloat16 *x2, *kvc2, *qc2, *ctx2, *wdown, *wup, *wq, *wout;
    __nv_bfloat16 *qbf, *kbf;
    __half *vh;
    cudaGetSymbolAddress((void**)&x2,    g_x2);
    cudaGetSymbolAddress((void**)&kvc2,  g_kvc2);
    cudaGetSymbolAddress((void**)&qc2,   g_qc2);
    cudaGetSymbolAddress((void**)&ctx2,  g_ctx2);
    cudaGetSymbolAddress((void**)&wdown, g_w_down);
    cudaGetSymbolAddress((void**)&wup,   g_w_up);
    cudaGetSymbolAddress((void**)&wq,    g_w_q);
    cudaGetSymbolAddress((void**)&wout,  g_w_out);
    cudaGetSymbolAddress((void**)&qbf,   g_qbf);
    cudaGetSymbolAddress((void**)&kbf,   g_kbf);
    cudaGetSymbolAddress((void**)&vh,    g_vh);

    cudaFuncSetAttribute(gemm_mma, cudaFuncAttributeMaxDynamicSharedMemorySize, GEMM_SMEM_BYTES);
    cudaFuncSetAttribute(attn_mma, cudaFuncAttributeMaxDynamicSharedMemorySize, AT_SMEM);

    // ---- operand conversion (stage 1): x + combined down weights ----
    launch_split(x,            x2,    S_LEN, HIDDEN, 1);
    launch_split(kv_down_w,    wdown,                         KVC, HIDDEN, 0);
    launch_split(query_down_w, wdown + (size_t)KVC*3*HIDDEN,  QC,  HIDDEN, 0);

    // ---- fused down projection: N = 512 + 1024 ----
    {
        Epi3 e;
        e.nend0 = KVC; e.nend1 = KVC + QC;
        e.s0 = { kv_down_b,    kv_c, 0,   KVC, KVC, 0, 0 };
        e.s1 = { query_down_b, q_c,  KVC, QC,  QC,  0, 0 };
        e.s2 = e.s1;
        gemm_mma<<<dim3((KVC + QC) / 128, S_LEN / 128), 256, GEMM_SMEM_BYTES>>>(
            x2, wdown, 3 * HIDDEN, e);
    }

    // ---- operand conversion (stage 2) ----
    launch_split(kv_c,         kvc2, S_LEN, KVC, 1);
    launch_split(q_c,          qc2,  S_LEN, QC,  1);
    launch_split(key_up_w,     wup,                          VROW, KVC, 0);
    launch_split(value_up_w,   wup + (size_t)VROW*3*KVC,     VROW, KVC, 0);
    launch_split(key_rope_w,   wup + (size_t)2*VROW*3*KVC,   NHEAD * RDIM, KVC, 0);
    launch_split(query_up_w,   wq,                           VROW, QC, 0);
    launch_split(query_rope_w, wq + (size_t)VROW*3*QC,       NHEAD * RDIM, QC, 0);

    // ---- fused kv up projection: N = 2048 + 2048 + 1024 ----
    {
        Epi3 e;
        e.nend0 = VROW; e.nend1 = 2 * VROW;
        e.s0 = { key_up_b,   keys,   0,        KROW,         HDIM,         DTOT, 0 };
        e.s1 = { value_up_b, values, VROW,     VROW,         VROW,         0,    0 };
        e.s2 = { key_rope_b, rraw,   2 * VROW, NHEAD * RDIM, NHEAD * RDIM, 0,    0 };
        gemm_mma<<<dim3((2 * VROW + NHEAD * RDIM) / 128, S_LEN / 128), 256, GEMM_SMEM_BYTES>>>(
            kvc2, wup, 3 * KVC, e);
    }
    {
        int n = S_LEN * NHEAD * (RDIM / 2);
        rope_kernel<<<(n + 255) / 256, 256>>>(rraw, keys);
    }

    // ---- fused q up projection: N = 2048 + 1024 ----
    {
        Epi3 e;
        e.nend0 = VROW; e.nend1 = VROW + NHEAD * RDIM;
        e.s0 = { query_up_b,   queries, 0,    KROW,         HDIM,         DTOT, 0 };
        e.s1 = { query_rope_b, rraw,    VROW, NHEAD * RDIM, NHEAD * RDIM, 0,    0 };
        e.s2 = e.s1;
        gemm_mma<<<dim3((VROW + NHEAD * RDIM) / 128, S_LEN / 128), 256, GEMM_SMEM_BYTES>>>(
            qc2, wq, 3 * QC, e);
    }
    {
        int n = S_LEN * NHEAD * (RDIM / 2);
        rope_kernel<<<(n + 255) / 256, 256>>>(rraw, queries);
    }

    // ---- per-head conversion ----
    {
        int tqk = NHEAD * S_LEN * (DTOT / 2);
        conv_head<<<(tqk + 255) / 256, 256>>>(queries, qbf, DTOT, KROW, tqk);
        conv_head<<<(tqk + 255) / 256, 256>>>(keys,    kbf, DTOT, KROW, tqk);
        int tv = NHEAD * S_LEN * (HDIM / 2);
        conv_head_f16<<<(tv + 255) / 256, 256>>>(values, vh, HDIM, VROW, tv);
    }

    // ---- tensor-core attention -> ctx ----
    attn_mma<<<dim3(S_LEN / 128, NHEAD), 256, AT_SMEM>>>(qbf, kbf, vh, ctx);

    // ---- output projection ----
    launch_split(ctx,   ctx2, S_LEN,  VROW, 1);
    launch_split(out_w, wout, HIDDEN, VROW, 0);
    {
        Epi3 e;
        e.nend0 = HIDDEN; e.nend1 = HIDDEN;
        e.s0 = { out_b, out, 0, HIDDEN, HIDDEN, 0, 0 };
        e.s1 = e.s0; e.s2 = e.s0;
        gemm_mma<<<dim3(HIDDEN / 128, S_LEN / 128), 256, GEMM_SMEM_BYTES>>>(
            ctx2, wout, 3 * VROW, e);
    }
}

// round 14
// speedup vs baseline: 4.9695x; 1.0435x over previous
#include <cuda_runtime.h>
#include <cuda_bf16.h>
#include <cuda_fp16.h>
#include <math.h>
#include <stdint.h>

#define S_LEN 2048
#define HIDDEN 2048
#define NHEAD 16
#define HDIM 128
#define RDIM 64
#define KVC 512
#define QC 1024
#define DTOT 192           // HDIM + RDIM
#define KROW (NHEAD*DTOT)  // 3072
#define VROW (NHEAD*HDIM)  // 2048

// ---------------- scratch ---------------------------------------------------
__device__ float g_rope_raw[S_LEN * NHEAD * RDIM];

// bf16x3 operand buffers ([hi|lo|hi] activations, [hi|hi|lo] weights)
__device__ __align__(1024) __nv_bfloat16 g_x2    [S_LEN * 3 * HIDDEN];
__device__ __align__(1024) __nv_bfloat16 g_kvc2  [S_LEN * 3 * KVC];
__device__ __align__(1024) __nv_bfloat16 g_qc2   [S_LEN * 3 * QC];
__device__ __align__(1024) __nv_bfloat16 g_ctx2  [S_LEN * 3 * VROW];
__device__ __align__(1024) __nv_bfloat16 g_w_down[(KVC + QC) * 3 * HIDDEN];
__device__ __align__(1024) __nv_bfloat16 g_w_up  [(VROW + VROW + NHEAD*RDIM) * 3 * KVC];
__device__ __align__(1024) __nv_bfloat16 g_w_q   [(VROW + NHEAD*RDIM) * 3 * QC];
__device__ __align__(1024) __nv_bfloat16 g_w_out [HIDDEN * 3 * VROW];

// per-head attention operands
__device__ __align__(1024) __nv_bfloat16 g_qbf[NHEAD * S_LEN * DTOT];
__device__ __align__(1024) __nv_bfloat16 g_kbf[NHEAD * S_LEN * DTOT];
__device__ __align__(1024) __half        g_vh [NHEAD * S_LEN * HDIM];

// ---------------- mma.sync helpers (sm_80 baseline PTX) --------------------
__device__ __forceinline__ uint32_t smem_u32(const void* p) {
    uint32_t a;
    asm("{ .reg .u64 t; cvta.to.shared.u64 t, %1; cvt.u32.u64 %0, t; }" : "=r"(a) : "l"(p));
    return a;
}
__device__ __forceinline__ uint32_t h2_as_u32(__half2 v) {
    return *reinterpret_cast<uint32_t*>(&v);
}
__device__ __forceinline__ uint32_t bf2_as_u32(__nv_bfloat162 v) {
    return *reinterpret_cast<uint32_t*>(&v);
}
__device__ __forceinline__ void ldsm4(uint32_t* r, uint32_t addr) {
    asm volatile("ldmatrix.sync.aligned.m8n8.x4.shared.b16 {%0,%1,%2,%3}, [%4];"
                 : "=r"(r[0]), "=r"(r[1]), "=r"(r[2]), "=r"(r[3]) : "r"(addr));
}
__device__ __forceinline__ void ldsm4t(uint32_t* r, uint32_t addr) {
    asm volatile("ldmatrix.sync.aligned.m8n8.x4.trans.shared.b16 {%0,%1,%2,%3}, [%4];"
                 : "=r"(r[0]), "=r"(r[1]), "=r"(r[2]), "=r"(r[3]) : "r"(addr));
}
__device__ __forceinline__ void mma16816(float* d, const uint32_t* a, uint32_t b0, uint32_t b1) {
    asm volatile("mma.sync.aligned.m16n8k16.row.col.f32.bf16.bf16.f32 "
                 "{%0,%1,%2,%3}, {%4,%5,%6,%7}, {%8,%9}, {%0,%1,%2,%3};"
                 : "+f"(d[0]), "+f"(d[1]), "+f"(d[2]), "+f"(d[3])
                 : "r"(a[0]), "r"(a[1]), "r"(a[2]), "r"(a[3]), "r"(b0), "r"(b1));
}
__device__ __forceinline__ void mma16816h(float* d, const uint32_t* a, uint32_t b0, uint32_t b1) {
    asm volatile("mma.sync.aligned.m16n8k16.row.col.f32.f16.f16.f32 "
                 "{%0,%1,%2,%3}, {%4,%5,%6,%7}, {%8,%9}, {%0,%1,%2,%3};"
                 : "+f"(d[0]), "+f"(d[1]), "+f"(d[2]), "+f"(d[3])
                 : "r"(a[0]), "r"(a[1]), "r"(a[2]), "r"(a[3]), "r"(b0), "r"(b1));
}
#define CP_ASYNC16(dst, src) \
    asm volatile("cp.async.cg.shared.global [%0], [%1], 16;" :: "r"(dst), "l"(src))
#define CP_COMMIT() asm volatile("cp.async.commit_group;" ::: "memory")
#define CP_WAIT2()  asm volatile("cp.async.wait_group 2;" ::: "memory")
#define CP_WAIT1()  asm volatile("cp.async.wait_group 1;" ::: "memory")

// ================= segment-routed epilogue descriptor ======================
// mode 0: fp32 scatter  (dst float*)
// mode 1: bf16 [hi|lo|hi] rows of next-GEMM A buffer (dst bf16*, rs = next K)
// mode 2: fp16 per-head [h][S][HDIM]  (dst half*)
// mode 3: bf16 per-head [h][S][DTOT] cols 0..127  (dst bf16*)
struct Seg { const float* bias; void* dst; int n0, rs, G, GS, CO, mode; };
struct Epi3 { int nend0, nend1; Seg s0, s1, s2; };

// ================= mma.sync NT GEMM with fused epilogue ====================
#define NSTAGE 4
#define STAGE_BYTES 8192
#define GEMM_SMEM_BYTES (NSTAGE * STAGE_BYTES * 2)   // 65536

__global__ __launch_bounds__(256, 2) void gemm_mma(
    const __nv_bfloat16* __restrict__ A, const __nv_bfloat16* __restrict__ B,
    int K, Epi3 e)
{
    extern __shared__ __align__(1024) char sm[];
    const uint32_t sbase = smem_u32(sm);
    const int tid = threadIdx.x;
    const int wid = tid >> 5, L = tid & 31;
    const int wm = wid >> 2, wn = wid & 3;
    const int bm = blockIdx.y * 128, bn = blockIdx.x * 128;
    const size_t rowb = (size_t)K * 2;
    const char* gA = (const char*)A + (size_t)bm * rowb;
    const char* gB = (const char*)B + (size_t)bn * rowb;

    const int u0 = tid, u1 = tid + 256;
    const int r0 = u0 >> 2, c0 = u0 & 3;
    const int r1 = u1 >> 2, c1 = u1 & 3;
    const uint32_t d0 = (uint32_t)(r0 * 64 + ((c0 ^ ((r0 >> 1) & 3)) * 16));
    const uint32_t d1 = (uint32_t)(r1 * 64 + ((c1 ^ ((r1 >> 1) & 3)) * 16));
    const size_t s0A = (size_t)r0 * rowb + c0 * 16;
    const size_t s1A = (size_t)r1 * rowb + c1 * 16;

    const int NC = K >> 5;

#define LOAD_STAGE(st) do {                                              \
        const int _s = (st) & 3;                                         \
        const int _k0 = (st) << 5;                                       \
        const uint32_t aB = sbase + _s * STAGE_BYTES;                    \
        const uint32_t bB = sbase + NSTAGE * STAGE_BYTES + _s * STAGE_BYTES; \
        CP_ASYNC16(aB + d0, gA + s0A + _k0 * 2);                         \
        CP_ASYNC16(aB + d1, gA + s1A + _k0 * 2);                         \
        CP_ASYNC16(bB + d0, gB + s0A + _k0 * 2);                         \
        CP_ASYNC16(bB + d1, gB + s1A + _k0 * 2);                         \
    } while (0)

    LOAD_STAGE(0); CP_COMMIT();
    LOAD_STAGE(1); CP_COMMIT();
    LOAD_STAGE(2); CP_COMMIT();

    float acc[4][4][4];
#pragma unroll
    for (int mi = 0; mi < 4; mi++)
#pragma unroll
        for (int ni = 0; ni < 4; ni++)
#pragma unroll
            for (int f = 0; f < 4; f++) acc[mi][ni][f] = 0.f;

    const int lr = L & 15;
    const int lku = L >> 4;

    for (int i = 0; i < NC; i++) {
        CP_WAIT2();
        __syncthreads();           // single barrier per iteration (see invariant)
        if (i + 3 < NC) LOAD_STAGE(i + 3);
        CP_COMMIT();

        const int buf = i & 3;
        const uint32_t aB = sbase + buf * STAGE_BYTES;
        const uint32_t bB = sbase + NSTAGE * STAGE_BYTES + buf * STAGE_BYTES;
#pragma unroll
        for (int ks = 0; ks < 2; ks++) {
            const int c16 = ks * 2 + lku;
            uint32_t afr[4][4], bfr[2][4];
#pragma unroll
            for (int nj = 0; nj < 2; nj++) {
                const int r = wn * 32 + nj * 16 + lr;
                ldsm4(bfr[nj], bB + r * 64 + ((c16 ^ ((r >> 1) & 3)) * 16));
            }
#pragma unroll
            for (int mi = 0; mi < 4; mi++) {
                const int r = wm * 64 + mi * 16 + lr;
                ldsm4(afr[mi], aB + r * 64 + ((c16 ^ ((r >> 1) & 3)) * 16));
            }
#pragma unroll
            for (int mi = 0; mi < 4; mi++)
#pragma unroll
                for (int ni = 0; ni < 4; ni++)
                    mma16816(acc[mi][ni], afr[mi],
                             bfr[ni >> 1][ni & 1], bfr[ni >> 1][(ni & 1) + 2]);
        }
    }
#undef LOAD_STAGE

    // epilogue: segment-routed (whole CTA tile lies in one segment)
    const Seg sg = (bn < e.nend0) ? e.s0 : (bn < e.nend1 ? e.s1 : e.s2);
    const int g = L >> 2, tg = L & 3;
#pragma unroll
    for (int mi = 0; mi < 4; mi++) {
#pragma unroll
        for (int ni = 0; ni < 4; ni++) {
            const int nl = bn + wn * 32 + ni * 8 + 2 * tg - sg.n0;
            const float b0 = sg.bias[nl], b1 = sg.bias[nl + 1];
            const int mlo = bm + wm * 64 + mi * 16 + g;
            const float v00 = acc[mi][ni][0] + b0, v01 = acc[mi][ni][1] + b1;
            const float v10 = acc[mi][ni][2] + b0, v11 = acc[mi][ni][3] + b1;
            if (sg.mode == 0) {
                float* D = (float*)sg.dst;
                const size_t ncol = (size_t)(nl / sg.G) * sg.GS + (nl % sg.G) + sg.CO;
                *(float2*)(D + (size_t)mlo * sg.rs + ncol) = make_float2(v00, v01);
                *(float2*)(D + (size_t)(mlo + 8) * sg.rs + ncol) = make_float2(v10, v11);
            } else if (sg.mode == 1) {
                __nv_bfloat16* D = (__nv_bfloat16*)sg.dst;
                const int Kn = sg.rs;
                size_t b0a = (size_t)mlo * 3 * Kn + nl;
                size_t b1a = (size_t)(mlo + 8) * 3 * Kn + nl;
                __nv_bfloat16 h00 = __float2bfloat16(v00), h01 = __float2bfloat16(v01);
                __nv_bfloat16 h10 = __float2bfloat16(v10), h11 = __float2bfloat16(v11);
                uint32_t hi0 = bf2_as_u32(__halves2bfloat162(h00, h01));
                uint32_t hi1 = bf2_as_u32(__halves2bfloat162(h10, h11));
                uint32_t lo0 = bf2_as_u32(__halves2bfloat162(
                    __float2bfloat16(v00 - __bfloat162float(h00)),
                    __float2bfloat16(v01 - __bfloat162float(h01))));
                uint32_t lo1 = bf2_as_u32(__halves2bfloat162(
                    __float2bfloat16(v10 - __bfloat162float(h10)),
                    __float2bfloat16(v11 - __bfloat162float(h11))));
                *(uint32_t*)(D + b0a) = hi0;          *(uint32_t*)(D + b1a) = hi1;
                *(uint32_t*)(D + b0a + Kn) = lo0;     *(uint32_t*)(D + b1a + Kn) = lo1;
                *(uint32_t*)(D + b0a + 2 * Kn) = hi0; *(uint32_t*)(D + b1a + 2 * Kn) = hi1;
            } else if (sg.mode == 2) {
                __half* D = (__half*)sg.dst;
                const size_t ncol = (size_t)(nl / sg.G) * sg.GS + (nl % sg.G) + sg.CO;
                *(__half2*)(D + (size_t)mlo * sg.rs + ncol) = __floats2half2_rn(v00, v01);
                *(__half2*)(D + (size_t)(mlo + 8) * sg.rs + ncol) = __floats2half2_rn(v10, v11);
            } else {
                __nv_bfloat16* D = (__nv_bfloat16*)sg.dst;
                const size_t ncol = (size_t)(nl / sg.G) * sg.GS + (nl % sg.G) + sg.CO;
                *(uint32_t*)(D + (size_t)mlo * sg.rs + ncol) =
                    bf2_as_u32(__floats2bfloat162_rn(v00, v01));
                *(uint32_t*)(D + (size_t)(mlo + 8) * sg.rs + ncol) =
                    bf2_as_u32(__floats2bfloat162_rn(v10, v11));
            }
        }
    }
}

// ---------------- fp32 -> bf16 hi/lo split+concat (inputs only) ------------
__global__ void split3(const float* __restrict__ src, __nv_bfloat16* __restrict__ dst,
                       int K, int total2, int modeA)
{
    int idx = blockIdx.x * blockDim.x + threadIdx.x;
    if (idx >= total2) return;
    const int k2 = K >> 1;
    const int row = idx / k2;
    const int kk = (idx - row * k2) * 2;
    float2 v = *(const float2*)(src + (size_t)row * K + kk);
    __nv_bfloat16 h0 = __float2bfloat16(v.x), h1 = __float2bfloat16(v.y);
    __nv_bfloat16 l0 = __float2bfloat16(v.x - __bfloat162float(h0));
    __nv_bfloat16 l1 = __float2bfloat16(v.y - __bfloat162float(h1));
    __nv_bfloat162 hh = __halves2bfloat162(h0, h1);
    __nv_bfloat162 ll = __halves2bfloat162(l0, l1);
    size_t base = (size_t)row * 3 * K + kk;
    *(__nv_bfloat162*)(dst + base)         = hh;
    *(__nv_bfloat162*)(dst + base + K)     = modeA ? ll : hh;
    *(__nv_bfloat162*)(dst + base + 2 * K) = modeA ? hh : ll;
}

// ---------------- RoPE -> per-head bf16 (positions = head index) -----------
__global__ void rope_kernel(const float* __restrict__ raw, __nv_bfloat16* __restrict__ dst)
{
    int idx = blockIdx.x * blockDim.x + threadIdx.x;
    if (idx >= S_LEN * NHEAD * (RDIM / 2)) return;
    int i = idx & 31;
    int h = (idx >> 5) & 15;
    int s = idx >> 9;
    size_t rb = (size_t)s * (NHEAD * RDIM) + h * RDIM + 2 * i;
    float x1 = raw[rb], x2 = raw[rb + 1];
    float inv_freq = powf(10000.f, -((float)(2 * i)) / (float)RDIM);
    float ang = (float)h * inv_freq;
    float sv, cv;
    sincosf(ang, &sv, &cv);
    size_t ob = ((size_t)h * S_LEN + s) * DTOT + HDIM + 2 * i;
    *(uint32_t*)(dst + ob) = bf2_as_u32(
        __floats2bfloat162_rn(x1 * cv - x2 * sv, x1 * sv + x2 * cv));
}

// ================= tensor-core flash attention =============================
// CTA: 128 q-rows x 1 head, 8 warps, k-tiles of 64, 2-stage cp.async.
// QK bf16, PV fp16.  Epilogue writes ctx2 [hi|lo|hi] bf16 directly.
#define AT_QPITCH 400
#define AT_KPITCH 400
#define AT_VPITCH 272
#define AT_QS 0
#define AT_KS (128 * AT_QPITCH)                     // 51200
#define AT_VS (AT_KS + 2 * 64 * AT_KPITCH)          // 102400
#define AT_SMEM (AT_VS + 2 * 64 * AT_VPITCH)        // 137216

__global__ __launch_bounds__(256) void attn_mma(
    const __nv_bfloat16* __restrict__ Qh, const __nv_bfloat16* __restrict__ Kh,
    const __half* __restrict__ Vh, __nv_bfloat16* __restrict__ ctx2)
{
    extern __shared__ __align__(1024) char sm[];
    const uint32_t sb = smem_u32(sm);
    const int tid = threadIdx.x;
    const int wq = tid >> 5, L = tid & 31;
    const int g = L >> 2, tg = L & 3;
    const int h = blockIdx.y, q0 = blockIdx.x * 128;
    const char* Qg = (const char*)(Qh + ((size_t)h * S_LEN + q0) * DTOT);
    const char* Kg = (const char*)(Kh + (size_t)h * S_LEN * DTOT);
    const char* Vg = (const char*)(Vh + (size_t)h * S_LEN * HDIM);

#pragma unroll
    for (int c = tid; c < 128 * 24; c += 256) {
        int r = c / 24, cc = c - r * 24;
        CP_ASYNC16(sb + AT_QS + r * AT_QPITCH + cc * 16, Qg + (size_t)r * 384 + cc * 16);
    }

#define LOADKV(t, buf) do {                                                   \
        const int _kv = (t) * 64;                                             \
        const uint32_t _kB = sb + AT_KS + (buf) * 64 * AT_KPITCH;             \
        const uint32_t _vB = sb + AT_VS + (buf) * 64 * AT_VPITCH;             \
        for (int _c = tid; _c < 64 * 24; _c += 256) {                         \
            int _r = _c / 24, _cc = _c - _r * 24;                             \
            CP_ASYNC16(_kB + _r * AT_KPITCH + _cc * 16,                       \
                       Kg + (size_t)(_kv + _r) * 384 + _cc * 16);             \
        }                                                                     \
        for (int _c = tid; _c < 64 * 16; _c += 256) {                         \
            int _r = _c >> 4, _cc = _c & 15;                                  \
            CP_ASYNC16(_vB + _r * AT_VPITCH + _cc * 16,                       \
                       Vg + (size_t)(_kv + _r) * 256 + _cc * 16);             \
        }                                                                     \
    } while (0)

    LOADKV(0, 0); CP_COMMIT();
    LOADKV(1, 1); CP_COMMIT();

    float ofr[16][4];
#pragma unroll
    for (int o = 0; o < 16; o++)
#pragma unroll
        for (int f = 0; f < 4; f++) ofr[o][f] = 0.f;
    float m0 = -INFINITY, m1 = -INFINITY, l0 = 0.f, l1 = 0.f;
    const float scale = rsqrtf((float)DTOT);

    const int arow = (L & 7) + ((L >> 3) & 1) * 8;
    const int acol = ((L >> 4) & 1) * 8;
    const int brow = (L & 7) + ((L >> 4) & 1) * 8;
    const int bcol = ((L >> 3) & 1) * 8;

    for (int t = 0; t < S_LEN / 64; t++) {
        CP_WAIT1();
        __syncthreads();
        const int buf = t & 1;
        const uint32_t kB = sb + AT_KS + buf * 64 * AT_KPITCH;
        const uint32_t vB = sb + AT_VS + buf * 64 * AT_VPITCH;

        float sfr[8][4];
#pragma unroll
        for (int ni = 0; ni < 8; ni++)
#pragma unroll
            for (int f = 0; f < 4; f++) sfr[ni][f] = 0.f;
#pragma unroll
        for (int d0 = 0; d0 < DTOT; d0 += 16) {
            uint32_t a[4];
            ldsm4(a, sb + AT_QS + (wq * 16 + arow) * AT_QPITCH + (d0 + acol) * 2);
#pragma unroll
            for (int nk = 0; nk < 4; nk++) {
                uint32_t b[4];
                ldsm4(b, kB + (nk * 16 + brow) * AT_KPITCH + (d0 + bcol) * 2);
                mma16816(sfr[2 * nk], a, b[0], b[1]);
                mma16816(sfr[2 * nk + 1], a, b[2], b[3]);
            }
        }

        float mx0 = -INFINITY, mx1 = -INFINITY;
#pragma unroll
        for (int ni = 0; ni < 8; ni++) {
            mx0 = fmaxf(mx0, fmaxf(sfr[ni][0], sfr[ni][1]));
            mx1 = fmaxf(mx1, fmaxf(sfr[ni][2], sfr[ni][3]));
        }
        mx0 *= scale; mx1 *= scale;
        mx0 = fmaxf(mx0, __shfl_xor_sync(0xffffffffu, mx0, 1));
        mx0 = fmaxf(mx0, __shfl_xor_sync(0xffffffffu, mx0, 2));
        mx1 = fmaxf(mx1, __shfl_xor_sync(0xffffffffu, mx1, 1));
        mx1 = fmaxf(mx1, __shfl_xor_sync(0xffffffffu, mx1, 2));
        const float mn0 = fmaxf(m0, mx0), mn1 = fmaxf(m1, mx1);
        const float e0 = __expf(m0 - mn0), e1 = __expf(m1 - mn1);
        m0 = mn0; m1 = mn1;
        l0 *= e0; l1 *= e1;
#pragma unroll
        for (int o = 0; o < 16; o++) {
            ofr[o][0] *= e0; ofr[o][1] *= e0;
            ofr[o][2] *= e1; ofr[o][3] *= e1;
        }
        uint32_t pfr[8][2];
        float sum0 = 0.f, sum1 = 0.f;
#pragma unroll
        for (int ni = 0; ni < 8; ni++) {
            float p0 = __expf(sfr[ni][0] * scale - mn0);
            float p1 = __expf(sfr[ni][1] * scale - mn0);
            float p2 = __expf(sfr[ni][2] * scale - mn1);
            float p3 = __expf(sfr[ni][3] * scale - mn1);
            sum0 += p0 + p1; sum1 += p2 + p3;
            pfr[ni][0] = h2_as_u32(__floats2half2_rn(p0, p1));
            pfr[ni][1] = h2_as_u32(__floats2half2_rn(p2, p3));
        }
        l0 += sum0; l1 += sum1;

#pragma unroll
        for (int kj = 0; kj < 4; kj++) {
            uint32_t a[4] = { pfr[2 * kj][0], pfr[2 * kj][1],
                              pfr[2 * kj + 1][0], pfr[2 * kj + 1][1] };
#pragma unroll
            for (int dt = 0; dt < 8; dt++) {
                uint32_t b[4];
                ldsm4t(b, vB + (kj * 16 + arow) * AT_VPITCH + (dt * 16 + acol) * 2);
                mma16816h(ofr[2 * dt], a, b[0], b[1]);
                mma16816h(ofr[2 * dt + 1], a, b[2], b[3]);
            }
        }

        __syncthreads();
        if (t + 2 < S_LEN / 64) LOADKV(t + 2, buf);
        CP_COMMIT();
    }
#undef LOADKV

    // epilogue: normalize + write ctx2 [hi|lo|hi] bf16 (row stride 3*VROW)
    float lt0 = l0 + __shfl_xor_sync(0xffffffffu, l0, 1);
    lt0 += __shfl_xor_sync(0xffffffffu, lt0, 2);
    float lt1 = l1 + __shfl_xor_sync(0xffffffffu, l1, 1);
    lt1 += __shfl_xor_sync(0xffffffffu, lt1, 2);
    const float inv0 = 1.f / lt0, inv1 = 1.f / lt1;
    const int r0 = q0 + wq * 16 + g, r1 = r0 + 8;
#pragma unroll
    for (int ni = 0; ni < 16; ni++) {
        const int col = h * HDIM + ni * 8 + 2 * tg;
        float a0 = ofr[ni][0] * inv0, a1 = ofr[ni][1] * inv0;
        float b0 = ofr[ni][2] * inv1, b1 = ofr[ni][3] * inv1;
        __nv_bfloat16 ha0 = __float2bfloat16(a0), ha1 = __float2bfloat16(a1);
        __nv_bfloat16 hb0 = __float2bfloat16(b0), hb1 = __float2bfloat16(b1);
        uint32_t hi0 = bf2_as_u32(__halves2bfloat162(ha0, ha1));
        uint32_t hi1 = bf2_as_u32(__halves2bfloat162(hb0, hb1));
        uint32_t lo0 = bf2_as_u32(__halves2bfloat162(
            __float2bfloat16(a0 - __bfloat162float(ha0)),
            __float2bfloat16(a1 - __bfloat162float(ha1))));
        uint32_t lo1 = bf2_as_u32(__halves2bfloat162(
            __float2bfloat16(b0 - __bfloat162float(hb0)),
            __float2bfloat16(b1 - __bfloat162float(hb1))));
        size_t ba0 = (size_t)r0 * 3 * VROW + col;
        size_t ba1 = (size_t)r1 * 3 * VROW + col;
        *(uint32_t*)(ctx2 + ba0) = hi0;            *(uint32_t*)(ctx2 + ba1) = hi1;
        *(uint32_t*)(ctx2 + ba0 + VROW) = lo0;     *(uint32_t*)(ctx2 + ba1 + VROW) = lo1;
        *(uint32_t*)(ctx2 + ba0 + 2 * VROW) = hi0; *(uint32_t*)(ctx2 + ba1 + 2 * VROW) = hi1;
    }
}

// ---------------- launcher -------------------------------------------------
static inline void launch_split(const float* src, __nv_bfloat16* dst, int M, int K, int modeA)
{
    int total2 = (M * K) >> 1;
    split3<<<(total2 + 255) / 256, 256>>>(src, dst, K, total2, modeA);
}

extern "C" void kernel_launch(void* const* d_in, const int* in_sizes, int n_in,
                              void* d_out, int out_size)
{
    const float* x            = (const float*)d_in[0];
    const float* kv_down_w    = (const float*)d_in[1];
    const float* kv_down_b    = (const float*)d_in[2];
    const float* key_up_w     = (const float*)d_in[3];
    const float* key_up_b     = (const float*)d_in[4];
    const float* value_up_w   = (const float*)d_in[5];
    const float* value_up_b   = (const float*)d_in[6];
    const float* key_rope_w   = (const float*)d_in[7];
    const float* key_rope_b   = (const float*)d_in[8];
    const float* query_down_w = (const float*)d_in[9];
    const float* query_down_b = (const float*)d_in[10];
    const float* query_up_w   = (const float*)d_in[11];
    const float* query_up_b   = (const float*)d_in[12];
    const float* query_rope_w = (const float*)d_in[13];
    const float* query_rope_b = (const float*)d_in[14];
    const float* out_w        = (const float*)d_in[15];
    const float* out_b        = (const float*)d_in[16];
    float* out = (float*)d_out;

    float* rraw;
    cudaGetSymbolAddress((void**)&rraw, g_rope_raw);
    __nv_bfloat16 *x2, *kvc2, *qc2, *ctx2, *wdown, *wup, *wq, *wout, *qbf, *kbf;
    __half *vh;
    cudaGetSymbolAddress((void**)&x2,    g_x2);
    cudaGetSymbolAddress((void**)&kvc2,  g_kvc2);
    cudaGetSymbolAddress((void**)&qc2,   g_qc2);
    cudaGetSymbolAddress((void**)&ctx2,  g_ctx2);
    cudaGetSymbolAddress((void**)&wdown, g_w_down);
    cudaGetSymbolAddress((void**)&wup,   g_w_up);
    cudaGetSymbolAddress((void**)&wq,    g_w_q);
    cudaGetSymbolAddress((void**)&wout,  g_w_out);
    cudaGetSymbolAddress((void**)&qbf,   g_qbf);
    cudaGetSymbolAddress((void**)&kbf,   g_kbf);
    cudaGetSymbolAddress((void**)&vh,    g_vh);

    cudaFuncSetAttribute(gemm_mma, cudaFuncAttributeMaxDynamicSharedMemorySize, GEMM_SMEM_BYTES);
    cudaFuncSetAttribute(attn_mma, cudaFuncAttributeMaxDynamicSharedMemorySize, AT_SMEM);

    // ---- input conversions ----
    launch_split(x,            x2,    S_LEN, HIDDEN, 1);
    launch_split(kv_down_w,    wdown,                        KVC, HIDDEN, 0);
    launch_split(query_down_w, wdown + (size_t)KVC*3*HIDDEN, QC,  HIDDEN, 0);
    launch_split(key_up_w,     wup,                          VROW, KVC, 0);
    launch_split(value_up_w,   wup + (size_t)VROW*3*KVC,     VROW, KVC, 0);
    launch_split(key_rope_w,   wup + (size_t)2*VROW*3*KVC,   NHEAD * RDIM, KVC, 0);
    launch_split(query_up_w,   wq,                           VROW, QC, 0);
    launch_split(query_rope_w, wq + (size_t)VROW*3*QC,       NHEAD * RDIM, QC, 0);
    launch_split(out_w,        wout,                         HIDDEN, VROW, 0);

    // ---- fused down projection: kvc2 + qc2 written as [hi|lo|hi] ----
    {
        Epi3 e;
        e.nend0 = KVC; e.nend1 = KVC + QC;
        e.s0 = { kv_down_b,    kvc2, 0,   KVC, 1, 1, 0, 1 };
        e.s1 = { query_down_b, qc2,  KVC, QC,  1, 1, 0, 1 };
        e.s2 = e.s1;
        gemm_mma<<<dim3((KVC + QC) / 128, S_LEN / 128), 256, GEMM_SMEM_BYTES>>>(
            x2, wdown, 3 * HIDDEN, e);
    }

    // ---- fused kv up projection: keys_c -> kbf, values -> vh, rope raw ----
    {
        Epi3 e;
        e.nend0 = VROW; e.nend1 = 2 * VROW;
        e.s0 = { key_up_b,   kbf,  0,        DTOT, HDIM, S_LEN * DTOT, 0, 3 };
        e.s1 = { value_up_b, vh,   VROW,     HDIM, HDIM, S_LEN * HDIM, 0, 2 };
        e.s2 = { key_rope_b, rraw, 2 * VROW, NHEAD * RDIM, NHEAD * RDIM, NHEAD * RDIM, 0, 0 };
        gemm_mma<<<dim3((2 * VROW + NHEAD * RDIM) / 128, S_LEN / 128), 256, GEMM_SMEM_BYTES>>>(
            kvc2, wup, 3 * KVC, e);
    }
    {
        int n = S_LEN * NHEAD * (RDIM / 2);
        rope_kernel<<<(n + 255) / 256, 256>>>(rraw, kbf);
    }

    // ---- fused q up projection: queries_c -> qbf, rope raw ----
    {
        Epi3 e;
        e.nend0 = VROW; e.nend1 = VROW + NHEAD * RDIM;
        e.s0 = { query_up_b,   qbf,  0,    DTOT, HDIM, S_LEN * DTOT, 0, 3 };
        e.s1 = { query_rope_b, rraw, VROW, NHEAD * RDIM, NHEAD * RDIM, NHEAD * RDIM, 0, 0 };
        e.s2 = e.s1;
        gemm_mma<<<dim3((VROW + NHEAD * RDIM) / 128, S_LEN / 128), 256, GEMM_SMEM_BYTES>>>(
            qc2, wq, 3 * QC, e);
    }
    {
        int n = S_LEN * NHEAD * (RDIM / 2);
        rope_kernel<<<(n + 255) / 256, 256>>>(rraw, qbf);
    }

    // ---- tensor-core attention -> ctx2 ([hi|lo|hi] written in epilogue) ----
    attn_mma<<<dim3(S_LEN / 128, NHEAD), 256, AT_SMEM>>>(qbf, kbf, vh, ctx2);

    // ---- output projection ----
    {
        Epi3 e;
        e.nend0 = HIDDEN; e.nend1 = HIDDEN;
        e.s0 = { out_b, out, 0, HIDDEN, HIDDEN, HIDDEN, 0, 0 };
        e.s1 = e.s0; e.s2 = e.s0;
        gemm_mma<<<dim3(HIDDEN / 128, S_LEN / 128), 256, GEMM_SMEM_BYTES>>>(
            ctx2, wout, 3 * VROW, e);
    }
}